// round 1
// baseline (speedup 1.0000x reference)
#include <cuda_runtime.h>
#include <math.h>

// ---------------- problem constants ----------------
#define NN     50000
#define FIN    256
#define HIDDIM 128
#define NHEADS 8
#define HDIM   16
#define NCLS   64
#define NEDGE  1250000
#define NBF    44
#define EPSV   1e-4f
#define ALPHAV 0.1f

// ---------------- scratch (device globals; no runtime alloc) ----------------
__device__ float g_B1[FIN * 512];          // packed [256][q|k|v|lin1] weights
__device__ float g_bias1[512];
__device__ float g_C1[(size_t)NN * 512];   // per-row: q[128] | k[128] | v[128] | gnn1[128]
__device__ float g_kmax[NHEADS];
__device__ float g_kcum[NHEADS * NBF];
__device__ float g_ctx[NHEADS * HDIM * NBF];   // layout [h][d][m]
__device__ float g_h[(size_t)NN * 256];    // elu(gnn1) | elu(trans)
__device__ float g_x0[(size_t)NN * NCLS];  // logits after lin2+elu
__device__ float g_ha[(size_t)NN * NCLS];
__device__ float g_hb[(size_t)NN * NCLS];
__device__ int   g_cnt[NN];
__device__ int   g_off[NN + 1];
__device__ int   g_cursor[NN];
__device__ float g_dis[NN];
__device__ int   g_csr_row[NEDGE];
__device__ float g_csr_norm[NEDGE];

// ---------------- helpers ----------------
__device__ __forceinline__ void atomicMaxFloat(float* addr, float val) {
    int* ia = (int*)addr;
    int old = *ia;
    while (__int_as_float(old) < val) {
        int assumed = old;
        old = atomicCAS(ia, assumed, __float_as_int(val));
        if (old == assumed) break;
    }
}

// ---------------- pack weights ----------------
__global__ void pack_kernel(const float* __restrict__ qw, const float* __restrict__ kw,
                            const float* __restrict__ vw, const float* __restrict__ l1w,
                            const float* __restrict__ qb, const float* __restrict__ kb,
                            const float* __restrict__ vb, const float* __restrict__ l1b) {
    int i = blockIdx.x * blockDim.x + threadIdx.x;
    if (i < FIN * 512) {
        int k = i >> 9, j = i & 511;
        const float* src = (j < 128) ? qw : (j < 256) ? kw : (j < 384) ? vw : l1w;
        g_B1[i] = src[k * 128 + (j & 127)];
    } else if (i < FIN * 512 + 512) {
        int j = i - FIN * 512;
        const float* sb = (j < 128) ? qb : (j < 256) ? kb : (j < 384) ? vb : l1b;
        g_bias1[j] = sb[j & 127];
    }
}

// ---------------- init ----------------
__global__ void init_kernel() {
    int i = blockIdx.x * blockDim.x + threadIdx.x;
    if (i < NHEADS) g_kmax[i] = -3e38f;
    if (i < NHEADS * NBF) g_kcum[i] = 0.f;
    if (i < NHEADS * HDIM * NBF) g_ctx[i] = 0.f;
    if (i < NN) g_cnt[i] = 0;
}

// ---------------- GEMM: MODE 0 = data@[q|k|v|lin1] -> g_C1 (512 cols)
//                  MODE 1 = g_h@lin2 + elu -> g_x0 (64 cols) ----------------
template <int MODE>
__global__ __launch_bounds__(256) void gemm_kernel(const float* __restrict__ Aext,
                                                   const float* __restrict__ Bext,
                                                   const float* __restrict__ bext) {
    constexpr int NCOL = (MODE == 0) ? 512 : NCLS;
    constexpr int K = 256;
    constexpr int BM = 128, BN = 64, BK = 16;
    const float* A = (MODE == 0) ? Aext : g_h;
    const float* B = (MODE == 0) ? g_B1 : Bext;
    const float* bias = (MODE == 0) ? g_bias1 : bext;
    float* C = (MODE == 0) ? g_C1 : g_x0;

    __shared__ float As[BK][BM];
    __shared__ float Bs[BK][BN];
    int t = threadIdx.x;
    int bm = blockIdx.x * BM, bn = blockIdx.y * BN;
    int ty = t >> 4, tx = t & 15;
    float acc[8][4];
#pragma unroll
    for (int i = 0; i < 8; i++)
#pragma unroll
        for (int j = 0; j < 4; j++) acc[i][j] = 0.f;

    int ar = t >> 2;          // 0..63
    int ak = (t & 3) * 4;     // 0,4,8,12
    int bkr = t >> 4;         // 0..15
    int bc = (t & 15) * 4;

    for (int k0 = 0; k0 < K; k0 += BK) {
#pragma unroll
        for (int i = 0; i < 2; i++) {
            int r = ar + i * 64;
            int gr = bm + r;
            float4 v = make_float4(0.f, 0.f, 0.f, 0.f);
            if (gr < NN) v = *(const float4*)&A[(size_t)gr * K + k0 + ak];
            As[ak][r] = v.x; As[ak + 1][r] = v.y; As[ak + 2][r] = v.z; As[ak + 3][r] = v.w;
        }
        *(float4*)&Bs[bkr][bc] = *(const float4*)&B[(size_t)(k0 + bkr) * NCOL + bn + bc];
        __syncthreads();
#pragma unroll
        for (int kk = 0; kk < BK; kk++) {
            float4 a0 = *(const float4*)&As[kk][ty * 8];
            float4 a1 = *(const float4*)&As[kk][ty * 8 + 4];
            float4 b0 = *(const float4*)&Bs[kk][tx * 4];
            float av[8] = {a0.x, a0.y, a0.z, a0.w, a1.x, a1.y, a1.z, a1.w};
            float bv[4] = {b0.x, b0.y, b0.z, b0.w};
#pragma unroll
            for (int i = 0; i < 8; i++)
#pragma unroll
                for (int j = 0; j < 4; j++) acc[i][j] += av[i] * bv[j];
        }
        __syncthreads();
    }
#pragma unroll
    for (int i = 0; i < 8; i++) {
        int gr = bm + ty * 8 + i;
        if (gr >= NN) continue;
#pragma unroll
        for (int j = 0; j < 4; j++) {
            float v = acc[i][j] + bias[bn + tx * 4 + j];
            if (MODE == 1) v = v > 0.f ? v : expm1f(v);
            C[(size_t)gr * NCOL + bn + tx * 4 + j] = v;
        }
    }
}

// ---------------- performer: global max of dash_k per head ----------------
__global__ __launch_bounds__(256) void kmax_kernel(const float* __restrict__ proj) {
    __shared__ float proj_s[NBF * HDIM];
    int t = threadIdx.x;
    for (int i = t; i < NBF * HDIM; i += 256) proj_s[i] = proj[i];
    __syncthreads();
    int n = blockIdx.x * 256 + t;
    float hm[NHEADS];
#pragma unroll
    for (int h = 0; h < NHEADS; h++) hm[h] = -3e38f;
    if (n < NN) {
        const float* base = &g_C1[(size_t)n * 512 + 128];  // k block
#pragma unroll
        for (int h = 0; h < NHEADS; h++) {
            float kr[HDIM];
#pragma unroll
            for (int d = 0; d < HDIM; d += 4) {
                float4 v = *(const float4*)&base[h * HDIM + d];
                kr[d] = v.x * 0.5f; kr[d + 1] = v.y * 0.5f; kr[d + 2] = v.z * 0.5f; kr[d + 3] = v.w * 0.5f;
            }
            float mx = -3e38f;
#pragma unroll
            for (int m = 0; m < NBF; m++) {
                float s = 0.f;
#pragma unroll
                for (int d = 0; d < HDIM; d++) s += kr[d] * proj_s[m * HDIM + d];
                mx = fmaxf(mx, s);
            }
            hm[h] = mx;
        }
    }
    int lane = t & 31;
#pragma unroll
    for (int h = 0; h < NHEADS; h++) {
#pragma unroll
        for (int o = 16; o > 0; o >>= 1)
            hm[h] = fmaxf(hm[h], __shfl_xor_sync(0xffffffffu, hm[h], o));
    }
    if (lane == 0) {
#pragma unroll
        for (int h = 0; h < NHEADS; h++) atomicMaxFloat(&g_kmax[h], hm[h]);
    }
}

// ---------------- performer: kp features -> k_cum + context ----------------
#define KP_BLOCKS 448
__global__ __launch_bounds__(256) void kp_acc_kernel(const float* __restrict__ proj) {
    __shared__ float proj_s[NBF * HDIM];
    __shared__ float kcum_s[NHEADS * NBF];
    __shared__ float ctx_s[NHEADS * HDIM * NBF];   // [h][d][m]
    __shared__ float kmax_s[NHEADS];
    int t = threadIdx.x;
    for (int i = t; i < NBF * HDIM; i += 256) proj_s[i] = proj[i];
    for (int i = t; i < NHEADS * NBF; i += 256) kcum_s[i] = 0.f;
    for (int i = t; i < NHEADS * HDIM * NBF; i += 256) ctx_s[i] = 0.f;
    if (t < NHEADS) kmax_s[t] = g_kmax[t];
    __syncthreads();

    int h = t >> 5;        // warp == head
    int lane = t & 31;
    const float ratio = rsqrtf((float)NBF);
    int chunk = (NN + KP_BLOCKS - 1) / KP_BLOCKS;
    int start = blockIdx.x * chunk;
    int end = min(start + chunk, NN);
    float kmaxh = kmax_s[h];

    for (int n = start; n < end; n++) {
        const float* kb = &g_C1[(size_t)n * 512 + 128 + h * HDIM];
        const float* vb = &g_C1[(size_t)n * 512 + 256 + h * HDIM];
        float kr[HDIM], vr[HDIM];
#pragma unroll
        for (int d = 0; d < HDIM; d += 4) {
            float4 kv = *(const float4*)&kb[d];
            float4 vv = *(const float4*)&vb[d];
            kr[d] = kv.x * 0.5f; kr[d + 1] = kv.y * 0.5f; kr[d + 2] = kv.z * 0.5f; kr[d + 3] = kv.w * 0.5f;
            vr[d] = vv.x; vr[d + 1] = vv.y; vr[d + 2] = vv.z; vr[d + 3] = vv.w;
        }
        float diag = 0.f;
#pragma unroll
        for (int d = 0; d < HDIM; d++) diag += kr[d] * kr[d];
        diag *= 0.5f;
#pragma unroll
        for (int rep = 0; rep < 2; rep++) {
            int mi = lane + rep * 32;
            if (mi < NBF) {
                float dash = 0.f;
#pragma unroll
                for (int d = 0; d < HDIM; d++) dash += kr[d] * proj_s[mi * HDIM + d];
                float kpv = ratio * (__expf(dash - diag - kmaxh) + EPSV);
                kcum_s[h * NBF + mi] += kpv;   // lane-owned: no race
#pragma unroll
                for (int d = 0; d < HDIM; d++)
                    ctx_s[(h * HDIM + d) * NBF + mi] += kpv * vr[d];
            }
        }
    }
    __syncthreads();
    for (int i = t; i < NHEADS * NBF; i += 256) atomicAdd(&g_kcum[i], kcum_s[i]);
    for (int i = t; i < NHEADS * HDIM * NBF; i += 256) atomicAdd(&g_ctx[i], ctx_s[i]);
}

// ---------------- attention output + h = elu(concat(gnn1, trans)) ----------------
__global__ __launch_bounds__(256) void attn_kernel(const float* __restrict__ proj) {
    __shared__ float proj_s[NBF * HDIM];
    __shared__ float kcum_s[NHEADS * NBF];
    __shared__ float ctx_s[NHEADS * HDIM * NBF];
    int t = threadIdx.x;
    for (int i = t; i < NBF * HDIM; i += 256) proj_s[i] = proj[i];
    for (int i = t; i < NHEADS * NBF; i += 256) kcum_s[i] = g_kcum[i];
    for (int i = t; i < NHEADS * HDIM * NBF; i += 256) ctx_s[i] = g_ctx[i];
    __syncthreads();

    int n = blockIdx.x * 256 + t;
    if (n >= NN) return;
    const float ratio = rsqrtf((float)NBF);
    const float* base = &g_C1[(size_t)n * 512];
    float* hrow = &g_h[(size_t)n * 256];

    // elu(gnn1)
#pragma unroll
    for (int j = 0; j < HIDDIM; j += 4) {
        float4 v = *(const float4*)&base[384 + j];
        v.x = v.x > 0.f ? v.x : expm1f(v.x);
        v.y = v.y > 0.f ? v.y : expm1f(v.y);
        v.z = v.z > 0.f ? v.z : expm1f(v.z);
        v.w = v.w > 0.f ? v.w : expm1f(v.w);
        *(float4*)&hrow[j] = v;
    }

    for (int h = 0; h < NHEADS; h++) {
        float q[HDIM];
#pragma unroll
        for (int d = 0; d < HDIM; d += 4) {
            float4 v = *(const float4*)&base[h * HDIM + d];
            q[d] = v.x * 0.5f; q[d + 1] = v.y * 0.5f; q[d + 2] = v.z * 0.5f; q[d + 3] = v.w * 0.5f;
        }
        float diag = 0.f;
#pragma unroll
        for (int d = 0; d < HDIM; d++) diag += q[d] * q[d];
        diag *= 0.5f;

        float dash[NBF];
        float qmax = -3e38f;
#pragma unroll
        for (int m = 0; m < NBF; m++) {
            float s = 0.f;
#pragma unroll
            for (int d = 0; d < HDIM; d++) s += q[d] * proj_s[m * HDIM + d];
            dash[m] = s;
            qmax = fmaxf(qmax, s);
        }
        float den = 0.f;
        float outv[HDIM];
#pragma unroll
        for (int d = 0; d < HDIM; d++) outv[d] = 0.f;
#pragma unroll
        for (int m = 0; m < NBF; m++) {
            float qp = ratio * (__expf(dash[m] - diag - qmax) + EPSV);
            den += qp * kcum_s[h * NBF + m];
#pragma unroll
            for (int d = 0; d < HDIM; d++) outv[d] += qp * ctx_s[(h * HDIM + d) * NBF + m];
        }
        float dinv = 1.f / den;
#pragma unroll
        for (int d = 0; d < HDIM; d++) {
            float v = outv[d] * dinv;
            hrow[HIDDIM + h * HDIM + d] = v > 0.f ? v : expm1f(v);
        }
    }
}

// ---------------- APPNP graph prep ----------------
__global__ void deg_kernel(const int* __restrict__ col) {
    int e = blockIdx.x * blockDim.x + threadIdx.x;
    if (e < NEDGE) atomicAdd(&g_cnt[col[e]], 1);
}

__global__ __launch_bounds__(1024) void scan_kernel() {
    __shared__ int tmp[1024];
    __shared__ int carry_s;
    int t = threadIdx.x;
    if (t == 0) carry_s = 0;
    __syncthreads();
    for (int base = 0; base < NN; base += 1024) {
        int i = base + t;
        int v = (i < NN) ? g_cnt[i] : 0;
        tmp[t] = v;
        __syncthreads();
#pragma unroll
        for (int s = 1; s < 1024; s <<= 1) {
            int u = (t >= s) ? tmp[t - s] : 0;
            __syncthreads();
            tmp[t] += u;
            __syncthreads();
        }
        int incl = tmp[t];
        int carry = carry_s;
        if (i < NN) {
            int off = carry + incl - v;
            g_off[i] = off;
            g_cursor[i] = off;
            g_dis[i] = rsqrtf((float)(v + 1));  // deg includes self loop
        }
        __syncthreads();
        if (t == 1023) carry_s = carry + incl;
        __syncthreads();
    }
    if (t == 0) g_off[NN] = carry_s;
}

__global__ void fill_kernel(const int* __restrict__ row, const int* __restrict__ col) {
    int e = blockIdx.x * blockDim.x + threadIdx.x;
    if (e >= NEDGE) return;
    int r = row[e], cl = col[e];
    int pos = atomicAdd(&g_cursor[cl], 1);
    g_csr_row[pos] = r;
    g_csr_norm[pos] = g_dis[r] * g_dis[cl];
}

// ---------------- APPNP hop ----------------
__global__ __launch_bounds__(64) void hop_kernel(int stage) {
    const float* src = (stage == 0) ? g_x0 : ((stage & 1) ? g_ha : g_hb);
    float* dst = (stage & 1) ? g_hb : g_ha;
    int i = blockIdx.x;
    int c = threadIdx.x;
    int s = g_off[i], e = g_off[i + 1];
    float di = g_dis[i];
    float acc = di * di * src[(size_t)i * NCLS + c];
    int j = s;
    for (; j + 4 <= e; j += 4) {
        int r0 = g_csr_row[j], r1 = g_csr_row[j + 1], r2 = g_csr_row[j + 2], r3 = g_csr_row[j + 3];
        float w0 = g_csr_norm[j], w1 = g_csr_norm[j + 1], w2 = g_csr_norm[j + 2], w3 = g_csr_norm[j + 3];
        acc += w0 * src[(size_t)r0 * NCLS + c];
        acc += w1 * src[(size_t)r1 * NCLS + c];
        acc += w2 * src[(size_t)r2 * NCLS + c];
        acc += w3 * src[(size_t)r3 * NCLS + c];
    }
    for (; j < e; j++)
        acc += g_csr_norm[j] * src[(size_t)g_csr_row[j] * NCLS + c];
    dst[(size_t)i * NCLS + c] = (1.f - ALPHAV) * acc + ALPHAV * g_x0[(size_t)i * NCLS + c];
}

// ---------------- log_softmax + write outputs ----------------
__global__ __launch_bounds__(256) void lsm_kernel(float* __restrict__ out, int out_size) {
    int gw = (blockIdx.x * blockDim.x + threadIdx.x) >> 5;
    int lane = threadIdx.x & 31;
    if (gw >= NN) return;
    const float* r = &g_hb[(size_t)gw * NCLS];
    float a = r[lane], b = r[lane + 32];
    float mx = fmaxf(a, b);
#pragma unroll
    for (int o = 16; o > 0; o >>= 1) mx = fmaxf(mx, __shfl_xor_sync(0xffffffffu, mx, o));
    float s = __expf(a - mx) + __expf(b - mx);
#pragma unroll
    for (int o = 16; o > 0; o >>= 1) s += __shfl_xor_sync(0xffffffffu, s, o);
    float lse = mx + logf(s);
    int i0 = gw * NCLS + lane;
    if (i0 < out_size) out[i0] = a - lse;
    if (i0 + 32 < out_size) out[i0 + 32] = b - lse;
    int j0 = NN * NCLS + i0;
    if (j0 < out_size) out[j0] = a;
    if (j0 + 32 < out_size) out[j0 + 32] = b;
}

// ---------------- launch ----------------
extern "C" void kernel_launch(void* const* d_in, const int* in_sizes, int n_in,
                              void* d_out, int out_size) {
    if (n_in < 13) return;
    const float* data = (const float*)d_in[0];
    const int* ei = (const int*)d_in[1];
    const float* l1w = (const float*)d_in[2];
    const float* l1b = (const float*)d_in[3];
    const float* l2w = (const float*)d_in[4];
    const float* l2b = (const float*)d_in[5];
    const float* qw = (const float*)d_in[6];
    const float* qb = (const float*)d_in[7];
    const float* kw = (const float*)d_in[8];
    const float* kb = (const float*)d_in[9];
    const float* vw = (const float*)d_in[10];
    const float* vb = (const float*)d_in[11];
    const float* proj = (const float*)d_in[12];
    const int* row = ei;
    const int* col = ei + NEDGE;

    pack_kernel<<<(FIN * 512 + 512 + 255) / 256, 256>>>(qw, kw, vw, l1w, qb, kb, vb, l1b);
    init_kernel<<<(NN + 255) / 256, 256>>>();

    dim3 g1((NN + 127) / 128, 512 / 64);
    gemm_kernel<0><<<g1, 256>>>(data, nullptr, nullptr);

    kmax_kernel<<<(NN + 255) / 256, 256>>>(proj);
    kp_acc_kernel<<<KP_BLOCKS, 256>>>(proj);
    attn_kernel<<<(NN + 255) / 256, 256>>>(proj);

    dim3 g2((NN + 127) / 128, 1);
    gemm_kernel<1><<<g2, 256>>>(nullptr, l2w, l2b);

    deg_kernel<<<(NEDGE + 255) / 256, 256>>>(col);
    scan_kernel<<<1, 1024>>>();
    fill_kernel<<<(NEDGE + 255) / 256, 256>>>(row, col);

    for (int k = 0; k < 10; k++)
        hop_kernel<<<NN, 64>>>(k);

    lsm_kernel<<<(NN * 32 + 255) / 256, 256>>>((float*)d_out, out_size);
}

// round 2
// speedup vs baseline: 1.3764x; 1.3764x over previous
#include <cuda_runtime.h>
#include <math.h>

// ---------------- problem constants ----------------
#define NN     50000
#define FIN    256
#define HIDDIM 128
#define NHEADS 8
#define HDIM   16
#define NCLS   64
#define NEDGE  1250000
#define NBF    44
#define EPSV   1e-4f
#define ALPHAV 0.1f

#define NTILES ((NN + 31) / 32)

// ---------------- scratch (device globals; no runtime alloc) ----------------
__device__ float g_B1[FIN * 512];          // packed [256][q|k|v|lin1] weights
__device__ float g_bias1[512];
__device__ float g_C1[(size_t)NN * 512];   // per-row: q[128] | k[128] | v[128] | gnn1[128]
__device__ float g_kmax[NHEADS];
__device__ float g_kcum[NHEADS * NBF];
__device__ float g_ctx[NHEADS * HDIM * NBF];   // layout [h][d][m]
__device__ float g_h[(size_t)NN * 256];    // elu(gnn1) | elu(trans)
__device__ float g_x0[(size_t)NN * NCLS];  // logits after lin2+elu
__device__ float g_ha[(size_t)NN * NCLS];
__device__ float g_hb[(size_t)NN * NCLS];
__device__ int   g_cnt[NN];
__device__ int   g_off[NN + 1];
__device__ int   g_cursor[NN];
__device__ float g_dis[NN];
__device__ int   g_csr_row[NEDGE];
__device__ float g_csr_norm[NEDGE];

// ---------------- helpers ----------------
__device__ __forceinline__ void atomicMaxFloat(float* addr, float val) {
    int* ia = (int*)addr;
    int old = *ia;
    while (__int_as_float(old) < val) {
        int assumed = old;
        old = atomicCAS(ia, assumed, __float_as_int(val));
        if (old == assumed) break;
    }
}

// Fast exp on the FMA pipe (no MUFU). rel err ~2.4e-6 on the range used here
// (arguments are always <= 0: dash - diag - max <= 0). Result feeds "+EPS".
__device__ __forceinline__ float fexp(float x) {
    float y = fmaxf(x * 1.44269504f, -125.0f);
    float z = y + 12582912.0f;               // 1.5*2^23 magic round
    int   n = __float_as_int(z) - 0x4B400000;
    float f = y - (z - 12582912.0f);         // f in [-0.5, 0.5]
    float q = 0.00133335581f;
    q = q * f + 0.00961812911f;
    q = q * f + 0.0555041087f;
    q = q * f + 0.240226507f;
    q = q * f + 0.693147181f;
    q = q * f + 1.0f;
    return q * __int_as_float((n + 127) << 23);
}

// ---------------- pack weights ----------------
__global__ void pack_kernel(const float* __restrict__ qw, const float* __restrict__ kw,
                            const float* __restrict__ vw, const float* __restrict__ l1w,
                            const float* __restrict__ qb, const float* __restrict__ kb,
                            const float* __restrict__ vb, const float* __restrict__ l1b) {
    int i = blockIdx.x * blockDim.x + threadIdx.x;
    if (i < FIN * 512) {
        int k = i >> 9, j = i & 511;
        const float* src = (j < 128) ? qw : (j < 256) ? kw : (j < 384) ? vw : l1w;
        g_B1[i] = src[k * 128 + (j & 127)];
    } else if (i < FIN * 512 + 512) {
        int j = i - FIN * 512;
        const float* sb = (j < 128) ? qb : (j < 256) ? kb : (j < 384) ? vb : l1b;
        g_bias1[j] = sb[j & 127];
    }
}

// ---------------- init ----------------
__global__ void init_kernel() {
    int i = blockIdx.x * blockDim.x + threadIdx.x;
    if (i < NHEADS) g_kmax[i] = -3e38f;
    if (i < NHEADS * NBF) g_kcum[i] = 0.f;
    if (i < NHEADS * HDIM * NBF) g_ctx[i] = 0.f;
    if (i < NN) g_cnt[i] = 0;
}

// ---------------- GEMM: MODE 0 = data@[q|k|v|lin1] -> g_C1 (512 cols)
//                  MODE 1 = g_h@lin2 + elu -> g_x0 (64 cols) ----------------
template <int MODE>
__global__ __launch_bounds__(256) void gemm_kernel(const float* __restrict__ Aext,
                                                   const float* __restrict__ Bext,
                                                   const float* __restrict__ bext) {
    constexpr int NCOL = (MODE == 0) ? 512 : NCLS;
    constexpr int K = 256;
    constexpr int BM = 128, BN = 64, BK = 16;
    const float* A = (MODE == 0) ? Aext : g_h;
    const float* B = (MODE == 0) ? g_B1 : Bext;
    const float* bias = (MODE == 0) ? g_bias1 : bext;
    float* C = (MODE == 0) ? g_C1 : g_x0;

    __shared__ float As[BK][BM];
    __shared__ float Bs[BK][BN];
    int t = threadIdx.x;
    int bm = blockIdx.x * BM, bn = blockIdx.y * BN;
    int ty = t >> 4, tx = t & 15;
    float acc[8][4];
#pragma unroll
    for (int i = 0; i < 8; i++)
#pragma unroll
        for (int j = 0; j < 4; j++) acc[i][j] = 0.f;

    int ar = t >> 2;
    int ak = (t & 3) * 4;
    int bkr = t >> 4;
    int bc = (t & 15) * 4;

    for (int k0 = 0; k0 < K; k0 += BK) {
#pragma unroll
        for (int i = 0; i < 2; i++) {
            int r = ar + i * 64;
            int gr = bm + r;
            float4 v = make_float4(0.f, 0.f, 0.f, 0.f);
            if (gr < NN) v = *(const float4*)&A[(size_t)gr * K + k0 + ak];
            As[ak][r] = v.x; As[ak + 1][r] = v.y; As[ak + 2][r] = v.z; As[ak + 3][r] = v.w;
        }
        *(float4*)&Bs[bkr][bc] = *(const float4*)&B[(size_t)(k0 + bkr) * NCOL + bn + bc];
        __syncthreads();
#pragma unroll
        for (int kk = 0; kk < BK; kk++) {
            float4 a0 = *(const float4*)&As[kk][ty * 8];
            float4 a1 = *(const float4*)&As[kk][ty * 8 + 4];
            float4 b0 = *(const float4*)&Bs[kk][tx * 4];
            float av[8] = {a0.x, a0.y, a0.z, a0.w, a1.x, a1.y, a1.z, a1.w};
            float bv[4] = {b0.x, b0.y, b0.z, b0.w};
#pragma unroll
            for (int i = 0; i < 8; i++)
#pragma unroll
                for (int j = 0; j < 4; j++) acc[i][j] += av[i] * bv[j];
        }
        __syncthreads();
    }
#pragma unroll
    for (int i = 0; i < 8; i++) {
        int gr = bm + ty * 8 + i;
        if (gr >= NN) continue;
#pragma unroll
        for (int j = 0; j < 4; j++) {
            float v = acc[i][j] + bias[bn + tx * 4 + j];
            if (MODE == 1) v = v > 0.f ? v : expm1f(v);
            C[(size_t)gr * NCOL + bn + tx * 4 + j] = v;
        }
    }
}

// ---------------- performer: global max of dash_k per head (tiled, coalesced) ----
__global__ __launch_bounds__(256) void kmax_kernel(const float* __restrict__ proj) {
    __shared__ float ks[128][33];
    __shared__ float proj_s[NBF * HDIM];
    int t = threadIdx.x;
    int row0 = blockIdx.x * 32;
    for (int i = t; i < NBF * HDIM; i += 256) proj_s[i] = proj[i];
    for (int i = t; i < 32 * 128; i += 256) {
        int r = i >> 7, d = i & 127;
        ks[d][r] = (row0 + r < NN) ? g_C1[(size_t)(row0 + r) * 512 + 128 + d] : 0.f;
    }
    __syncthreads();
    int h = t >> 5, r = t & 31;
    float mx = -3e38f;
    if (row0 + r < NN) {
        float k[HDIM];
#pragma unroll
        for (int d = 0; d < HDIM; d++) k[d] = ks[h * HDIM + d][r] * 0.5f;
#pragma unroll
        for (int m = 0; m < NBF; m++) {
            float s = 0.f;
#pragma unroll
            for (int d = 0; d < HDIM; d++) s += k[d] * proj_s[m * HDIM + d];
            mx = fmaxf(mx, s);
        }
    }
#pragma unroll
    for (int o = 16; o > 0; o >>= 1) mx = fmaxf(mx, __shfl_xor_sync(0xffffffffu, mx, o));
    if (r == 0) atomicMaxFloat(&g_kmax[h], mx);
}

// ---------------- performer: kp features -> k_cum + context (register ctx) ----
#define KPB 224
__global__ __launch_bounds__(352) void kp_acc_kernel(const float* __restrict__ proj) {
    __shared__ float s[256][33];   // [k(128)|v(128)][row], transposed, padded
    int t = threadIdx.x;
    int h = t / NBF, m = t - h * NBF;   // t < 352 -> h in [0,8)
    float pm[HDIM];
#pragma unroll
    for (int d = 0; d < HDIM; d++) pm[d] = proj[m * HDIM + d];
    float kmaxh = g_kmax[h];
    const float ratio = rsqrtf((float)NBF);
    float ctx[HDIM];
    float kc = 0.f;
#pragma unroll
    for (int d = 0; d < HDIM; d++) ctx[d] = 0.f;

    for (int tile = blockIdx.x; tile < NTILES; tile += gridDim.x) {
        int row0 = tile * 32;
        __syncthreads();
        for (int i = t; i < 32 * 256; i += 352) {
            int r = i >> 8, d = i & 255;
            s[d][r] = (row0 + r < NN) ? g_C1[(size_t)(row0 + r) * 512 + 128 + d] : 0.f;
        }
        __syncthreads();
        int rmax = min(32, NN - row0);
        for (int r = 0; r < rmax; r++) {
            float dash = 0.f, diag = 0.f;
#pragma unroll
            for (int d = 0; d < HDIM; d++) {
                float kv = s[h * HDIM + d][r] * 0.5f;
                dash += kv * pm[d];
                diag += kv * kv;
            }
            float kpv = ratio * (fexp(dash - 0.5f * diag - kmaxh) + EPSV);
            kc += kpv;
#pragma unroll
            for (int d = 0; d < HDIM; d++) ctx[d] += kpv * s[128 + h * HDIM + d][r];
        }
    }
    atomicAdd(&g_kcum[h * NBF + m], kc);
#pragma unroll
    for (int d = 0; d < HDIM; d++) atomicAdd(&g_ctx[(h * HDIM + d) * NBF + m], ctx[d]);
}

// ---------------- attention output + h = elu(concat(gnn1, trans)) (tiled) ----
__global__ __launch_bounds__(256) void attn_kernel(const float* __restrict__ proj) {
    __shared__ float qs[128][33];
    __shared__ float proj_s[NBF * HDIM];
    __shared__ float kcum_s[NHEADS * NBF];
    __shared__ float ctx_s[NHEADS * HDIM * NBF];
    int t = threadIdx.x;
    int row0 = blockIdx.x * 32;
    for (int i = t; i < NBF * HDIM; i += 256) proj_s[i] = proj[i];
    for (int i = t; i < NHEADS * NBF; i += 256) kcum_s[i] = g_kcum[i];
    for (int i = t; i < NHEADS * HDIM * NBF; i += 256) ctx_s[i] = g_ctx[i];
    for (int i = t; i < 32 * 128; i += 256) {
        int r = i >> 7, d = i & 127;
        qs[d][r] = (row0 + r < NN) ? g_C1[(size_t)(row0 + r) * 512 + d] : 0.f;
    }
    // elu(gnn1) coalesced pass (independent of staged q tile)
    for (int i = t; i < 32 * 128; i += 256) {
        int r = i >> 7, d = i & 127;
        if (row0 + r < NN) {
            float v = g_C1[(size_t)(row0 + r) * 512 + 384 + d];
            g_h[(size_t)(row0 + r) * 256 + d] = v > 0.f ? v : expm1f(v);
        }
    }
    __syncthreads();
    int h = t >> 5, r = t & 31;
    if (row0 + r >= NN) return;
    float q[HDIM];
    float diag = 0.f;
#pragma unroll
    for (int d = 0; d < HDIM; d++) {
        q[d] = qs[h * HDIM + d][r] * 0.5f;
        diag += q[d] * q[d];
    }
    diag *= 0.5f;
    float dash[NBF];
    float qmax = -3e38f;
#pragma unroll
    for (int m = 0; m < NBF; m++) {
        float s = 0.f;
#pragma unroll
        for (int d = 0; d < HDIM; d++) s += q[d] * proj_s[m * HDIM + d];
        dash[m] = s;
        qmax = fmaxf(qmax, s);
    }
    float den = 0.f;
    float outv[HDIM];
#pragma unroll
    for (int d = 0; d < HDIM; d++) outv[d] = 0.f;
    const float ratio = rsqrtf((float)NBF);
#pragma unroll
    for (int m = 0; m < NBF; m++) {
        float qp = ratio * (fexp(dash[m] - diag - qmax) + EPSV);
        den += qp * kcum_s[h * NBF + m];
#pragma unroll
        for (int d = 0; d < HDIM; d++) outv[d] += qp * ctx_s[(h * HDIM + d) * NBF + m];
    }
    float dinv = 1.f / den;
    float* hrow = &g_h[(size_t)(row0 + r) * 256 + HIDDIM + h * HDIM];
#pragma unroll
    for (int d = 0; d < HDIM; d++) {
        float v = outv[d] * dinv;
        hrow[d] = v > 0.f ? v : expm1f(v);
    }
}

// ---------------- APPNP graph prep ----------------
__global__ void deg_kernel(const int* __restrict__ col) {
    int e = blockIdx.x * blockDim.x + threadIdx.x;
    if (e < NEDGE) atomicAdd(&g_cnt[col[e]], 1);
}

__global__ __launch_bounds__(1024) void scan_kernel() {
    __shared__ int tmp[1024];
    __shared__ int carry_s;
    int t = threadIdx.x;
    if (t == 0) carry_s = 0;
    __syncthreads();
    for (int base = 0; base < NN; base += 1024) {
        int i = base + t;
        int v = (i < NN) ? g_cnt[i] : 0;
        tmp[t] = v;
        __syncthreads();
#pragma unroll
        for (int s = 1; s < 1024; s <<= 1) {
            int u = (t >= s) ? tmp[t - s] : 0;
            __syncthreads();
            tmp[t] += u;
            __syncthreads();
        }
        int incl = tmp[t];
        int carry = carry_s;
        if (i < NN) {
            int off = carry + incl - v;
            g_off[i] = off;
            g_cursor[i] = off;
            g_dis[i] = rsqrtf((float)(v + 1));  // deg includes self loop
        }
        __syncthreads();
        if (t == 1023) carry_s = carry + incl;
        __syncthreads();
    }
    if (t == 0) g_off[NN] = carry_s;
}

__global__ void fill_kernel(const int* __restrict__ row, const int* __restrict__ col) {
    int e = blockIdx.x * blockDim.x + threadIdx.x;
    if (e >= NEDGE) return;
    int r = row[e], cl = col[e];
    int pos = atomicAdd(&g_cursor[cl], 1);
    g_csr_row[pos] = r;
    g_csr_norm[pos] = g_dis[r] * g_dis[cl];
}

// ---------------- APPNP hop ----------------
__global__ __launch_bounds__(64) void hop_kernel(int stage) {
    const float* src = (stage == 0) ? g_x0 : ((stage & 1) ? g_ha : g_hb);
    float* dst = (stage & 1) ? g_hb : g_ha;
    int i = blockIdx.x;
    int c = threadIdx.x;
    int s = g_off[i], e = g_off[i + 1];
    float di = g_dis[i];
    float acc = di * di * src[(size_t)i * NCLS + c];
    int j = s;
    for (; j + 4 <= e; j += 4) {
        int r0 = g_csr_row[j], r1 = g_csr_row[j + 1], r2 = g_csr_row[j + 2], r3 = g_csr_row[j + 3];
        float w0 = g_csr_norm[j], w1 = g_csr_norm[j + 1], w2 = g_csr_norm[j + 2], w3 = g_csr_norm[j + 3];
        acc += w0 * src[(size_t)r0 * NCLS + c];
        acc += w1 * src[(size_t)r1 * NCLS + c];
        acc += w2 * src[(size_t)r2 * NCLS + c];
        acc += w3 * src[(size_t)r3 * NCLS + c];
    }
    for (; j < e; j++)
        acc += g_csr_norm[j] * src[(size_t)g_csr_row[j] * NCLS + c];
    dst[(size_t)i * NCLS + c] = (1.f - ALPHAV) * acc + ALPHAV * g_x0[(size_t)i * NCLS + c];
}

// ---------------- log_softmax + write outputs ----------------
__global__ __launch_bounds__(256) void lsm_kernel(float* __restrict__ out, int out_size) {
    int gw = (blockIdx.x * blockDim.x + threadIdx.x) >> 5;
    int lane = threadIdx.x & 31;
    if (gw >= NN) return;
    const float* r = &g_hb[(size_t)gw * NCLS];
    float a = r[lane], b = r[lane + 32];
    float mx = fmaxf(a, b);
#pragma unroll
    for (int o = 16; o > 0; o >>= 1) mx = fmaxf(mx, __shfl_xor_sync(0xffffffffu, mx, o));
    float s = __expf(a - mx) + __expf(b - mx);
#pragma unroll
    for (int o = 16; o > 0; o >>= 1) s += __shfl_xor_sync(0xffffffffu, s, o);
    float lse = mx + logf(s);
    int i0 = gw * NCLS + lane;
    if (i0 < out_size) out[i0] = a - lse;
    if (i0 + 32 < out_size) out[i0 + 32] = b - lse;
    int j0 = NN * NCLS + i0;
    if (j0 < out_size) out[j0] = a;
    if (j0 + 32 < out_size) out[j0 + 32] = b;
}

// ---------------- launch ----------------
extern "C" void kernel_launch(void* const* d_in, const int* in_sizes, int n_in,
                              void* d_out, int out_size) {
    if (n_in < 13) return;
    const float* data = (const float*)d_in[0];
    const int* ei = (const int*)d_in[1];
    const float* l1w = (const float*)d_in[2];
    const float* l1b = (const float*)d_in[3];
    const float* l2w = (const float*)d_in[4];
    const float* l2b = (const float*)d_in[5];
    const float* qw = (const float*)d_in[6];
    const float* qb = (const float*)d_in[7];
    const float* kw = (const float*)d_in[8];
    const float* kb = (const float*)d_in[9];
    const float* vw = (const float*)d_in[10];
    const float* vb = (const float*)d_in[11];
    const float* proj = (const float*)d_in[12];
    const int* row = ei;
    const int* col = ei + NEDGE;

    pack_kernel<<<(FIN * 512 + 512 + 255) / 256, 256>>>(qw, kw, vw, l1w, qb, kb, vb, l1b);
    init_kernel<<<(NN + 255) / 256, 256>>>();

    dim3 g1((NN + 127) / 128, 512 / 64);
    gemm_kernel<0><<<g1, 256>>>(data, nullptr, nullptr);

    kmax_kernel<<<NTILES, 256>>>(proj);
    kp_acc_kernel<<<KPB, 352>>>(proj);
    attn_kernel<<<NTILES, 256>>>(proj);

    dim3 g2((NN + 127) / 128, 1);
    gemm_kernel<1><<<g2, 256>>>(nullptr, l2w, l2b);

    deg_kernel<<<(NEDGE + 255) / 256, 256>>>(col);
    scan_kernel<<<1, 1024>>>();
    fill_kernel<<<(NEDGE + 255) / 256, 256>>>(row, col);

    for (int k = 0; k < 10; k++)
        hop_kernel<<<NN, 64>>>(k);

    lsm_kernel<<<(NN * 32 + 255) / 256, 256>>>((float*)d_out, out_size);
}

// round 4
// speedup vs baseline: 1.6016x; 1.1636x over previous
#include <cuda_runtime.h>
#include <cuda_bf16.h>
#include <math.h>
#include <stdint.h>

// ---------------- problem constants ----------------
#define NN     50000
#define FIN    256
#define HIDDIM 128
#define NHEADS 8
#define HDIM   16
#define NCLS   64
#define NEDGE  1250000
#define NBF    44
#define EPSV   1e-4f
#define ALPHAV 0.1f

#define NTILES ((NN + 31) / 32)

// ---------------- scratch (device globals; no runtime alloc) ----------------
__device__ float g_bias1[512];
__device__ __nv_bfloat16 g_Bt_hi[512 * 256];   // [n][k] transposed packed weights
__device__ __nv_bfloat16 g_Bt_lo[512 * 256];
__device__ __nv_bfloat16 g_A_hi[(size_t)NN * 256];
__device__ __nv_bfloat16 g_A_lo[(size_t)NN * 256];
__device__ float g_C1[(size_t)NN * 512];   // per-row: q[128] | k[128] | v[128] | gnn1[128]
__device__ float g_kmax[NHEADS];
__device__ float g_kcum[NHEADS * NBF];
__device__ float g_ctx[NHEADS * HDIM * NBF];   // layout [h][d][m]
__device__ float g_h[(size_t)NN * 256];    // elu(gnn1) | elu(trans)
__device__ float g_x0[(size_t)NN * NCLS];  // logits after lin2+elu
__device__ float g_ha[(size_t)NN * NCLS];
__device__ float g_hb[(size_t)NN * NCLS];
__device__ int   g_cnt[NN];
__device__ int   g_off[NN + 1];
__device__ int   g_cursor[NN];
__device__ float g_dis[NN];
__device__ int   g_csr_row[NEDGE];
__device__ float g_csr_norm[NEDGE];

// ---------------- PTX helpers ----------------
__device__ __forceinline__ uint32_t smem_u32(const void* p) {
    uint32_t a;
    asm("{ .reg .u64 t; cvta.to.shared.u64 t, %1; cvt.u32.u64 %0, t; }" : "=r"(a) : "l"(p));
    return a;
}
#define LDMX4(r0, r1, r2, r3, addr)                                          \
    asm volatile("ldmatrix.sync.aligned.m8n8.x4.shared.b16 {%0,%1,%2,%3}, [%4];" \
                 : "=r"(r0), "=r"(r1), "=r"(r2), "=r"(r3) : "r"(addr))
#define MMA16816(c, a, b0v, b1v)                                             \
    asm volatile("mma.sync.aligned.m16n8k16.row.col.f32.bf16.bf16.f32 "      \
                 "{%0,%1,%2,%3},{%4,%5,%6,%7},{%8,%9},{%0,%1,%2,%3};"        \
                 : "+f"((c)[0]), "+f"((c)[1]), "+f"((c)[2]), "+f"((c)[3])    \
                 : "r"((a)[0]), "r"((a)[1]), "r"((a)[2]), "r"((a)[3]),       \
                   "r"(b0v), "r"(b1v))

// ---------------- misc helpers ----------------
__device__ __forceinline__ void atomicMaxFloat(float* addr, float val) {
    int* ia = (int*)addr;
    int old = *ia;
    while (__int_as_float(old) < val) {
        int assumed = old;
        old = atomicCAS(ia, assumed, __float_as_int(val));
        if (old == assumed) break;
    }
}

__device__ __forceinline__ float fexp(float x) {
    float y = fmaxf(x * 1.44269504f, -125.0f);
    float z = y + 12582912.0f;
    int   n = __float_as_int(z) - 0x4B400000;
    float f = y - (z - 12582912.0f);
    float q = 0.00133335581f;
    q = q * f + 0.00961812911f;
    q = q * f + 0.0555041087f;
    q = q * f + 0.240226507f;
    q = q * f + 0.693147181f;
    q = q * f + 1.0f;
    return q * __int_as_float((n + 127) << 23);
}

// ---------------- pack weights: bias + transposed split-bf16 B ----------------
__global__ void pack_kernel(const float* __restrict__ qw, const float* __restrict__ kw,
                            const float* __restrict__ vw, const float* __restrict__ l1w,
                            const float* __restrict__ qb, const float* __restrict__ kb,
                            const float* __restrict__ vb, const float* __restrict__ l1b) {
    int i = blockIdx.x * blockDim.x + threadIdx.x;
    if (i < 512 * 256) {
        int n = i >> 8, k = i & 255;
        const float* src = (n < 128) ? qw : (n < 256) ? kw : (n < 384) ? vw : l1w;
        float w = src[k * 128 + (n & 127)];
        __nv_bfloat16 hi = __float2bfloat16(w);
        __nv_bfloat16 lo = __float2bfloat16(w - __bfloat162float(hi));
        g_Bt_hi[i] = hi;
        g_Bt_lo[i] = lo;
    } else if (i < 512 * 256 + 512) {
        int j = i - 512 * 256;
        const float* sb = (j < 128) ? qb : (j < 256) ? kb : (j < 384) ? vb : l1b;
        g_bias1[j] = sb[j & 127];
    }
}

// ---------------- split data to hi/lo bf16 ----------------
__global__ void conv_kernel(const float* __restrict__ A) {
    size_t i4 = (size_t)blockIdx.x * blockDim.x + threadIdx.x;
    size_t base = i4 * 4;
    if (base >= (size_t)NN * 256) return;
    float4 v = *(const float4*)&A[base];
    __nv_bfloat16 h0 = __float2bfloat16(v.x), h1 = __float2bfloat16(v.y);
    __nv_bfloat16 h2 = __float2bfloat16(v.z), h3 = __float2bfloat16(v.w);
    __nv_bfloat16 l0 = __float2bfloat16(v.x - __bfloat162float(h0));
    __nv_bfloat16 l1 = __float2bfloat16(v.y - __bfloat162float(h1));
    __nv_bfloat16 l2 = __float2bfloat16(v.z - __bfloat162float(h2));
    __nv_bfloat16 l3 = __float2bfloat16(v.w - __bfloat162float(h3));
    __nv_bfloat162* ph = (__nv_bfloat162*)&g_A_hi[base];
    ph[0] = __nv_bfloat162(h0, h1);
    ph[1] = __nv_bfloat162(h2, h3);
    __nv_bfloat162* pl = (__nv_bfloat162*)&g_A_lo[base];
    pl[0] = __nv_bfloat162(l0, l1);
    pl[1] = __nv_bfloat162(l2, l3);
}

// ---------------- init ----------------
__global__ void init_kernel() {
    int i = blockIdx.x * blockDim.x + threadIdx.x;
    if (i < NHEADS) g_kmax[i] = -3e38f;
    if (i < NHEADS * NBF) g_kcum[i] = 0.f;
    if (i < NHEADS * HDIM * NBF) g_ctx[i] = 0.f;
    if (i < NN) g_cnt[i] = 0;
}

// ---------------- HMMA split-bf16 GEMM: A[NN,256] @ Bt^T -> g_C1[NN,512] ----------
// CTA 128x128, 8 warps (4x2), warp 32x64. K staged in 64-chunks.
// smem tile [128 rows][64 k] bf16 = 128B/row; 16B-chunk swizzle: chunk ^= row&7.
#define HG_SMEM 65536
__global__ __launch_bounds__(256) void hmma_gemm_kernel() {
    extern __shared__ char smem[];
    const uint32_t sb = smem_u32(smem);
    const int t = threadIdx.x;
    const int w = t >> 5;
    const int lane = t & 31;
    const int wm = w >> 1, wn = w & 1;
    const int bm = blockIdx.x * 128;
    const int bn = blockIdx.y * 128;
    const uint32_t AH = 0, AL = 16384, BH = 32768, BL = 49152;

    float acc[2][8][4];
#pragma unroll
    for (int i = 0; i < 2; i++)
#pragma unroll
        for (int j = 0; j < 8; j++)
#pragma unroll
            for (int k = 0; k < 4; k++) acc[i][j][k] = 0.f;

    const int srow = t >> 3;       // 0..31
    const int schk = t & 7;        // 16B chunk in row
    const uint4 zero4 = make_uint4(0u, 0u, 0u, 0u);

    for (int c = 0; c < 4; c++) {
        const int k0 = c * 64;
        if (c) __syncthreads();
        // ---- stage 4 tiles (AH, AL, BH, BL), each 128 rows x 64 bf16 ----
#pragma unroll
        for (int rep = 0; rep < 4; rep++) {
            int row = rep * 32 + srow;
            uint32_t so = (uint32_t)(row * 128 + ((schk ^ (row & 7)) << 4));
            size_t ga = (size_t)(bm + row) * 256 + k0 + schk * 8;
            bool in = (bm + row) < NN;
            *(uint4*)(smem + AH + so) = in ? *(const uint4*)&g_A_hi[ga] : zero4;
            *(uint4*)(smem + AL + so) = in ? *(const uint4*)&g_A_lo[ga] : zero4;
            size_t gb = (size_t)(bn + row) * 256 + k0 + schk * 8;
            *(uint4*)(smem + BH + so) = *(const uint4*)&g_Bt_hi[gb];
            *(uint4*)(smem + BL + so) = *(const uint4*)&g_Bt_lo[gb];
        }
        __syncthreads();
        // ---- 4 k16-steps ----
#pragma unroll
        for (int ks = 0; ks < 4; ks++) {
            uint32_t ah[2][4], al[2][4], bh[4][4], bl[4][4];
            int lr = lane & 15;          // row within 16
            int kh = lane >> 4;          // k half
            int chunk = ks * 2 + kh;
#pragma unroll
            for (int im = 0; im < 2; im++) {
                int row = wm * 32 + im * 16 + lr;
                uint32_t so = (uint32_t)(row * 128 + ((chunk ^ (row & 7)) << 4));
                LDMX4(ah[im][0], ah[im][1], ah[im][2], ah[im][3], sb + AH + so);
                LDMX4(al[im][0], al[im][1], al[im][2], al[im][3], sb + AL + so);
            }
#pragma unroll
            for (int in = 0; in < 4; in++) {
                int row = wn * 64 + in * 16 + lr;
                uint32_t so = (uint32_t)(row * 128 + ((chunk ^ (row & 7)) << 4));
                LDMX4(bh[in][0], bh[in][1], bh[in][2], bh[in][3], sb + BH + so);
                LDMX4(bl[in][0], bl[in][1], bl[in][2], bl[in][3], sb + BL + so);
            }
#pragma unroll
            for (int im = 0; im < 2; im++) {
#pragma unroll
                for (int in = 0; in < 4; in++) {
                    MMA16816(acc[im][2 * in],     ah[im], bh[in][0], bh[in][2]);
                    MMA16816(acc[im][2 * in + 1], ah[im], bh[in][1], bh[in][3]);
                    MMA16816(acc[im][2 * in],     ah[im], bl[in][0], bl[in][2]);
                    MMA16816(acc[im][2 * in + 1], ah[im], bl[in][1], bl[in][3]);
                    MMA16816(acc[im][2 * in],     al[im], bh[in][0], bh[in][2]);
                    MMA16816(acc[im][2 * in + 1], al[im], bh[in][1], bh[in][3]);
                }
            }
        }
    }
    // ---- epilogue ----
    int gid = lane >> 2, tig = lane & 3;
#pragma unroll
    for (int im = 0; im < 2; im++) {
        int m0 = bm + wm * 32 + im * 16 + gid;
#pragma unroll
        for (int s = 0; s < 8; s++) {
            int n = bn + wn * 64 + s * 8 + tig * 2;
            float b0 = g_bias1[n], b1 = g_bias1[n + 1];
            if (m0 < NN) {
                float2 v = make_float2(acc[im][s][0] + b0, acc[im][s][1] + b1);
                *(float2*)&g_C1[(size_t)m0 * 512 + n] = v;
            }
            if (m0 + 8 < NN) {
                float2 v = make_float2(acc[im][s][2] + b0, acc[im][s][3] + b1);
                *(float2*)&g_C1[(size_t)(m0 + 8) * 512 + n] = v;
            }
        }
    }
}

// ---------------- small FFMA GEMM: g_h @ lin2 + elu -> g_x0 ----------------
__global__ __launch_bounds__(256) void gemm2_kernel(const float* __restrict__ Bext,
                                                    const float* __restrict__ bext) {
    constexpr int NCOL = NCLS;
    constexpr int K = 256;
    constexpr int BM = 128, BN = 64, BK = 16;
    const float* A = g_h;

    __shared__ float As[BK][BM];
    __shared__ float Bs[BK][BN];
    int t = threadIdx.x;
    int bm = blockIdx.x * BM, bn = 0;
    int ty = t >> 4, tx = t & 15;
    float acc[8][4];
#pragma unroll
    for (int i = 0; i < 8; i++)
#pragma unroll
        for (int j = 0; j < 4; j++) acc[i][j] = 0.f;

    int ar = t >> 2;
    int ak = (t & 3) * 4;
    int bkr = t >> 4;
    int bc = (t & 15) * 4;

    for (int k0 = 0; k0 < K; k0 += BK) {
#pragma unroll
        for (int i = 0; i < 2; i++) {
            int r = ar + i * 64;
            int gr = bm + r;
            float4 v = make_float4(0.f, 0.f, 0.f, 0.f);
            if (gr < NN) v = *(const float4*)&A[(size_t)gr * K + k0 + ak];
            As[ak][r] = v.x; As[ak + 1][r] = v.y; As[ak + 2][r] = v.z; As[ak + 3][r] = v.w;
        }
        *(float4*)&Bs[bkr][bc] = *(const float4*)&Bext[(size_t)(k0 + bkr) * NCOL + bn + bc];
        __syncthreads();
#pragma unroll
        for (int kk = 0; kk < BK; kk++) {
            float4 a0 = *(const float4*)&As[kk][ty * 8];
            float4 a1 = *(const float4*)&As[kk][ty * 8 + 4];
            float4 b0 = *(const float4*)&Bs[kk][tx * 4];
            float av[8] = {a0.x, a0.y, a0.z, a0.w, a1.x, a1.y, a1.z, a1.w};
            float bv[4] = {b0.x, b0.y, b0.z, b0.w};
#pragma unroll
            for (int i = 0; i < 8; i++)
#pragma unroll
                for (int j = 0; j < 4; j++) acc[i][j] += av[i] * bv[j];
        }
        __syncthreads();
    }
#pragma unroll
    for (int i = 0; i < 8; i++) {
        int gr = bm + ty * 8 + i;
        if (gr >= NN) continue;
#pragma unroll
        for (int j = 0; j < 4; j++) {
            float v = acc[i][j] + bext[bn + tx * 4 + j];
            v = v > 0.f ? v : expm1f(v);
            g_x0[(size_t)gr * NCOL + bn + tx * 4 + j] = v;
        }
    }
}

// ---------------- performer: global max of dash_k per head (tiled, coalesced) ----
__global__ __launch_bounds__(256) void kmax_kernel(const float* __restrict__ proj) {
    __shared__ float ks[128][33];
    __shared__ float proj_s[NBF * HDIM];
    int t = threadIdx.x;
    int row0 = blockIdx.x * 32;
    for (int i = t; i < NBF * HDIM; i += 256) proj_s[i] = proj[i];
    for (int i = t; i < 32 * 128; i += 256) {
        int r = i >> 7, d = i & 127;
        ks[d][r] = (row0 + r < NN) ? g_C1[(size_t)(row0 + r) * 512 + 128 + d] : 0.f;
    }
    __syncthreads();
    int h = t >> 5, r = t & 31;
    float mx = -3e38f;
    if (row0 + r < NN) {
        float k[HDIM];
#pragma unroll
        for (int d = 0; d < HDIM; d++) k[d] = ks[h * HDIM + d][r] * 0.5f;
#pragma unroll
        for (int m = 0; m < NBF; m++) {
            float s = 0.f;
#pragma unroll
            for (int d = 0; d < HDIM; d++) s += k[d] * proj_s[m * HDIM + d];
            mx = fmaxf(mx, s);
        }
    }
#pragma unroll
    for (int o = 16; o > 0; o >>= 1) mx = fmaxf(mx, __shfl_xor_sync(0xffffffffu, mx, o));
    if (r == 0) atomicMaxFloat(&g_kmax[h], mx);
}

// ---------------- performer: kp features -> k_cum + context (register ctx) ----
#define KPB 224
__global__ __launch_bounds__(352) void kp_acc_kernel(const float* __restrict__ proj) {
    __shared__ float s[256][33];
    int t = threadIdx.x;
    int h = t / NBF, m = t - h * NBF;
    float pm[HDIM];
#pragma unroll
    for (int d = 0; d < HDIM; d++) pm[d] = proj[m * HDIM + d];
    float kmaxh = g_kmax[h];
    const float ratio = rsqrtf((float)NBF);
    float ctx[HDIM];
    float kc = 0.f;
#pragma unroll
    for (int d = 0; d < HDIM; d++) ctx[d] = 0.f;

    for (int tile = blockIdx.x; tile < NTILES; tile += gridDim.x) {
        int row0 = tile * 32;
        __syncthreads();
        for (int i = t; i < 32 * 256; i += 352) {
            int r = i >> 8, d = i & 255;
            s[d][r] = (row0 + r < NN) ? g_C1[(size_t)(row0 + r) * 512 + 128 + d] : 0.f;
        }
        __syncthreads();
        int rmax = min(32, NN - row0);
        for (int r = 0; r < rmax; r++) {
            float dash = 0.f, diag = 0.f;
#pragma unroll
            for (int d = 0; d < HDIM; d++) {
                float kv = s[h * HDIM + d][r] * 0.5f;
                dash += kv * pm[d];
                diag += kv * kv;
            }
            float kpv = ratio * (fexp(dash - 0.5f * diag - kmaxh) + EPSV);
            kc += kpv;
#pragma unroll
            for (int d = 0; d < HDIM; d++) ctx[d] += kpv * s[128 + h * HDIM + d][r];
        }
    }
    atomicAdd(&g_kcum[h * NBF + m], kc);
#pragma unroll
    for (int d = 0; d < HDIM; d++) atomicAdd(&g_ctx[(h * HDIM + d) * NBF + m], ctx[d]);
}

// ---------------- attention output + h = elu(concat(gnn1, trans)) (tiled) ----
__global__ __launch_bounds__(256) void attn_kernel(const float* __restrict__ proj) {
    __shared__ float qs[128][33];
    __shared__ float proj_s[NBF * HDIM];
    __shared__ float kcum_s[NHEADS * NBF];
    __shared__ float ctx_s[NHEADS * HDIM * NBF];
    int t = threadIdx.x;
    int row0 = blockIdx.x * 32;
    for (int i = t; i < NBF * HDIM; i += 256) proj_s[i] = proj[i];
    for (int i = t; i < NHEADS * NBF; i += 256) kcum_s[i] = g_kcum[i];
    for (int i = t; i < NHEADS * HDIM * NBF; i += 256) ctx_s[i] = g_ctx[i];
    for (int i = t; i < 32 * 128; i += 256) {
        int r = i >> 7, d = i & 127;
        qs[d][r] = (row0 + r < NN) ? g_C1[(size_t)(row0 + r) * 512 + d] : 0.f;
    }
    for (int i = t; i < 32 * 128; i += 256) {
        int r = i >> 7, d = i & 127;
        if (row0 + r < NN) {
            float v = g_C1[(size_t)(row0 + r) * 512 + 384 + d];
            g_h[(size_t)(row0 + r) * 256 + d] = v > 0.f ? v : expm1f(v);
        }
    }
    __syncthreads();
    int h = t >> 5, r = t & 31;
    if (row0 + r >= NN) return;
    float q[HDIM];
    float diag = 0.f;
#pragma unroll
    for (int d = 0; d < HDIM; d++) {
        q[d] = qs[h * HDIM + d][r] * 0.5f;
        diag += q[d] * q[d];
    }
    diag *= 0.5f;
    float dash[NBF];
    float qmax = -3e38f;
#pragma unroll
    for (int m = 0; m < NBF; m++) {
        float s = 0.f;
#pragma unroll
        for (int d = 0; d < HDIM; d++) s += q[d] * proj_s[m * HDIM + d];
        dash[m] = s;
        qmax = fmaxf(qmax, s);
    }
    float den = 0.f;
    float outv[HDIM];
#pragma unroll
    for (int d = 0; d < HDIM; d++) outv[d] = 0.f;
    const float ratio = rsqrtf((float)NBF);
#pragma unroll
    for (int m = 0; m < NBF; m++) {
        float qp = ratio * (fexp(dash[m] - diag - qmax) + EPSV);
        den += qp * kcum_s[h * NBF + m];
#pragma unroll
        for (int d = 0; d < HDIM; d++) outv[d] += qp * ctx_s[(h * HDIM + d) * NBF + m];
    }
    float dinv = 1.f / den;
    float* hrow = &g_h[(size_t)(row0 + r) * 256 + HIDDIM + h * HDIM];
#pragma unroll
    for (int d = 0; d < HDIM; d++) {
        float v = outv[d] * dinv;
        hrow[d] = v > 0.f ? v : expm1f(v);
    }
}

// ---------------- APPNP graph prep ----------------
__global__ void deg_kernel(const int* __restrict__ col) {
    int e = blockIdx.x * blockDim.x + threadIdx.x;
    if (e < NEDGE) atomicAdd(&g_cnt[col[e]], 1);
}

__global__ __launch_bounds__(1024) void scan_kernel() {
    __shared__ int tmp[1024];
    __shared__ int carry_s;
    int t = threadIdx.x;
    if (t == 0) carry_s = 0;
    __syncthreads();
    for (int base = 0; base < NN; base += 1024) {
        int i = base + t;
        int v = (i < NN) ? g_cnt[i] : 0;
        tmp[t] = v;
        __syncthreads();
#pragma unroll
        for (int s = 1; s < 1024; s <<= 1) {
            int u = (t >= s) ? tmp[t - s] : 0;
            __syncthreads();
            tmp[t] += u;
            __syncthreads();
        }
        int incl = tmp[t];
        int carry = carry_s;
        if (i < NN) {
            int off = carry + incl - v;
            g_off[i] = off;
            g_cursor[i] = off;
            g_dis[i] = rsqrtf((float)(v + 1));
        }
        __syncthreads();
        if (t == 1023) carry_s = carry + incl;
        __syncthreads();
    }
    if (t == 0) g_off[NN] = carry_s;
}

__global__ void fill_kernel(const int* __restrict__ row, const int* __restrict__ col) {
    int e = blockIdx.x * blockDim.x + threadIdx.x;
    if (e >= NEDGE) return;
    int r = row[e], cl = col[e];
    int pos = atomicAdd(&g_cursor[cl], 1);
    g_csr_row[pos] = r;
    g_csr_norm[pos] = g_dis[r] * g_dis[cl];
}

// ---------------- APPNP hop ----------------
__global__ __launch_bounds__(64) void hop_kernel(int stage) {
    const float* src = (stage == 0) ? g_x0 : ((stage & 1) ? g_ha : g_hb);
    float* dst = (stage & 1) ? g_hb : g_ha;
    int i = blockIdx.x;
    int c = threadIdx.x;
    int s = g_off[i], e = g_off[i + 1];
    float di = g_dis[i];
    float acc = di * di * src[(size_t)i * NCLS + c];
    int j = s;
    for (; j + 4 <= e; j += 4) {
        int r0 = g_csr_row[j], r1 = g_csr_row[j + 1], r2 = g_csr_row[j + 2], r3 = g_csr_row[j + 3];
        float w0 = g_csr_norm[j], w1 = g_csr_norm[j + 1], w2 = g_csr_norm[j + 2], w3 = g_csr_norm[j + 3];
        acc += w0 * src[(size_t)r0 * NCLS + c];
        acc += w1 * src[(size_t)r1 * NCLS + c];
        acc += w2 * src[(size_t)r2 * NCLS + c];
        acc += w3 * src[(size_t)r3 * NCLS + c];
    }
    for (; j < e; j++)
        acc += g_csr_norm[j] * src[(size_t)g_csr_row[j] * NCLS + c];
    dst[(size_t)i * NCLS + c] = (1.f - ALPHAV) * acc + ALPHAV * g_x0[(size_t)i * NCLS + c];
}

// ---------------- log_softmax + write outputs ----------------
__global__ __launch_bounds__(256) void lsm_kernel(float* __restrict__ out, int out_size) {
    int gw = (blockIdx.x * blockDim.x + threadIdx.x) >> 5;
    int lane = threadIdx.x & 31;
    if (gw >= NN) return;
    const float* r = &g_hb[(size_t)gw * NCLS];
    float a = r[lane], b = r[lane + 32];
    float mx = fmaxf(a, b);
#pragma unroll
    for (int o = 16; o > 0; o >>= 1) mx = fmaxf(mx, __shfl_xor_sync(0xffffffffu, mx, o));
    float s = __expf(a - mx) + __expf(b - mx);
#pragma unroll
    for (int o = 16; o > 0; o >>= 1) s += __shfl_xor_sync(0xffffffffu, s, o);
    float lse = mx + logf(s);
    int i0 = gw * NCLS + lane;
    if (i0 < out_size) out[i0] = a - lse;
    if (i0 + 32 < out_size) out[i0 + 32] = b - lse;
    int j0 = NN * NCLS + i0;
    if (j0 < out_size) out[j0] = a;
    if (j0 + 32 < out_size) out[j0 + 32] = b;
}

// ---------------- launch ----------------
extern "C" void kernel_launch(void* const* d_in, const int* in_sizes, int n_in,
                              void* d_out, int out_size) {
    if (n_in < 13) return;
    const float* data = (const float*)d_in[0];
    const int* ei = (const int*)d_in[1];
    const float* l1w = (const float*)d_in[2];
    const float* l1b = (const float*)d_in[3];
    const float* l2w = (const float*)d_in[4];
    const float* l2b = (const float*)d_in[5];
    const float* qw = (const float*)d_in[6];
    const float* qb = (const float*)d_in[7];
    const float* kw = (const float*)d_in[8];
    const float* kb = (const float*)d_in[9];
    const float* vw = (const float*)d_in[10];
    const float* vb = (const float*)d_in[11];
    const float* proj = (const float*)d_in[12];
    const int* row = ei;
    const int* col = ei + NEDGE;

    cudaFuncSetAttribute(hmma_gemm_kernel, cudaFuncAttributeMaxDynamicSharedMemorySize, HG_SMEM);

    pack_kernel<<<(512 * 256 + 512 + 255) / 256, 256>>>(qw, kw, vw, l1w, qb, kb, vb, l1b);
    conv_kernel<<<(NN * 256 / 4 + 255) / 256, 256>>>(data);
    init_kernel<<<(NN + 255) / 256, 256>>>();

    dim3 g1((NN + 127) / 128, 4);
    hmma_gemm_kernel<<<g1, 256, HG_SMEM>>>();

    kmax_kernel<<<NTILES, 256>>>(proj);
    kp_acc_kernel<<<KPB, 352>>>(proj);
    attn_kernel<<<NTILES, 256>>>(proj);

    gemm2_kernel<<<(NN + 127) / 128, 256>>>(l2w, l2b);

    deg_kernel<<<(NEDGE + 255) / 256, 256>>>(col);
    scan_kernel<<<1, 1024>>>();
    fill_kernel<<<(NEDGE + 255) / 256, 256>>>(row, col);

    for (int k = 0; k < 10; k++)
        hop_kernel<<<NN, 64>>>(k);

    lsm_kernel<<<(NN * 32 + 255) / 256, 256>>>((float*)d_out, out_size);
}

// round 5
// speedup vs baseline: 1.8056x; 1.1274x over previous
#include <cuda_runtime.h>
#include <cuda_bf16.h>
#include <math.h>
#include <stdint.h>

// ---------------- problem constants ----------------
#define NN     50000
#define FIN    256
#define HIDDIM 128
#define NHEADS 8
#define HDIM   16
#define NCLS   64
#define NEDGE  1250000
#define NBF    44
#define EPSV   1e-4f
#define ALPHAV 0.1f

#define NTILES ((NN + 31) / 32)

// ---------------- scratch (device globals; no runtime alloc) ----------------
__device__ float g_bias1[512];
__device__ __nv_bfloat16 g_Bt_hi[512 * 256];   // [n][k] transposed packed qkv|lin1
__device__ __nv_bfloat16 g_Bt_lo[512 * 256];
__device__ __nv_bfloat16 g_B2_hi[64 * 256];    // [n][k] transposed lin2
__device__ __nv_bfloat16 g_B2_lo[64 * 256];
__device__ __nv_bfloat16 g_A_hi[(size_t)NN * 256];
__device__ __nv_bfloat16 g_A_lo[(size_t)NN * 256];
__device__ float g_C1[(size_t)NN * 512];   // per-row: q[128] | k[128] | v[128] | gnn1[128]
__device__ float g_kmax[NHEADS];
__device__ float g_kcum[NHEADS * NBF];
__device__ float g_ctx[NHEADS * HDIM * NBF];   // layout [h][d][m]
__device__ __nv_bfloat16 g_h_hi[(size_t)NN * 256];   // elu(gnn1)|elu(trans), split bf16
__device__ __nv_bfloat16 g_h_lo[(size_t)NN * 256];
__device__ float g_x0[(size_t)NN * NCLS];  // logits after lin2+elu
__device__ float g_ha[(size_t)NN * NCLS];
__device__ float g_hb[(size_t)NN * NCLS];
__device__ int   g_cnt[NN];
__device__ int   g_off[NN + 1];
__device__ int   g_cursor[NN];
__device__ float g_dis[NN];
__device__ int   g_csr_row[NEDGE];
__device__ float g_csr_norm[NEDGE];

// ---------------- PTX helpers ----------------
__device__ __forceinline__ uint32_t smem_u32(const void* p) {
    uint32_t a;
    asm("{ .reg .u64 t; cvta.to.shared.u64 t, %1; cvt.u32.u64 %0, t; }" : "=r"(a) : "l"(p));
    return a;
}
#define LDMX4(r0, r1, r2, r3, addr)                                          \
    asm volatile("ldmatrix.sync.aligned.m8n8.x4.shared.b16 {%0,%1,%2,%3}, [%4];" \
                 : "=r"(r0), "=r"(r1), "=r"(r2), "=r"(r3) : "r"(addr))
#define MMA16816(c, a, b0v, b1v)                                             \
    asm volatile("mma.sync.aligned.m16n8k16.row.col.f32.bf16.bf16.f32 "      \
                 "{%0,%1,%2,%3},{%4,%5,%6,%7},{%8,%9},{%0,%1,%2,%3};"        \
                 : "+f"((c)[0]), "+f"((c)[1]), "+f"((c)[2]), "+f"((c)[3])    \
                 : "r"((a)[0]), "r"((a)[1]), "r"((a)[2]), "r"((a)[3]),       \
                   "r"(b0v), "r"(b1v))
__device__ __forceinline__ void cp_async16(uint32_t saddr, const void* gaddr, uint32_t srcsize) {
    asm volatile("cp.async.cg.shared.global [%0], [%1], 16, %2;"
                 :: "r"(saddr), "l"(gaddr), "r"(srcsize) : "memory");
}
#define CP_COMMIT() asm volatile("cp.async.commit_group;" ::: "memory")
#define CP_WAIT1()  asm volatile("cp.async.wait_group 1;" ::: "memory")
#define CP_WAIT0()  asm volatile("cp.async.wait_group 0;" ::: "memory")

// ---------------- misc helpers ----------------
__device__ __forceinline__ void atomicMaxFloat(float* addr, float val) {
    int* ia = (int*)addr;
    int old = *ia;
    while (__int_as_float(old) < val) {
        int assumed = old;
        old = atomicCAS(ia, assumed, __float_as_int(val));
        if (old == assumed) break;
    }
}

__device__ __forceinline__ float fexp(float x) {
    float y = fmaxf(x * 1.44269504f, -125.0f);
    float z = y + 12582912.0f;
    int   n = __float_as_int(z) - 0x4B400000;
    float f = y - (z - 12582912.0f);
    float q = 0.00133335581f;
    q = q * f + 0.00961812911f;
    q = q * f + 0.0555041087f;
    q = q * f + 0.240226507f;
    q = q * f + 0.693147181f;
    q = q * f + 1.0f;
    return q * __int_as_float((n + 127) << 23);
}

// ---------------- pack weights: bias + transposed split-bf16 B1, B2 ----------------
__global__ void pack_kernel(const float* __restrict__ qw, const float* __restrict__ kw,
                            const float* __restrict__ vw, const float* __restrict__ l1w,
                            const float* __restrict__ qb, const float* __restrict__ kb,
                            const float* __restrict__ vb, const float* __restrict__ l1b,
                            const float* __restrict__ l2w) {
    int i = blockIdx.x * blockDim.x + threadIdx.x;
    if (i < 512 * 256) {
        int n = i >> 8, k = i & 255;
        const float* src = (n < 128) ? qw : (n < 256) ? kw : (n < 384) ? vw : l1w;
        float w = src[k * 128 + (n & 127)];
        __nv_bfloat16 hi = __float2bfloat16(w);
        g_Bt_hi[i] = hi;
        g_Bt_lo[i] = __float2bfloat16(w - __bfloat162float(hi));
    } else if (i < 512 * 256 + 512) {
        int j = i - 512 * 256;
        const float* sb = (j < 128) ? qb : (j < 256) ? kb : (j < 384) ? vb : l1b;
        g_bias1[j] = sb[j & 127];
    } else if (i < 512 * 256 + 512 + 64 * 256) {
        int i2 = i - (512 * 256 + 512);
        int n = i2 >> 8, k = i2 & 255;
        float w = l2w[k * 64 + n];
        __nv_bfloat16 hi = __float2bfloat16(w);
        g_B2_hi[i2] = hi;
        g_B2_lo[i2] = __float2bfloat16(w - __bfloat162float(hi));
    }
}

// ---------------- split data to hi/lo bf16 ----------------
__global__ void conv_kernel(const float* __restrict__ A) {
    size_t i4 = (size_t)blockIdx.x * blockDim.x + threadIdx.x;
    size_t base = i4 * 4;
    if (base >= (size_t)NN * 256) return;
    float4 v = *(const float4*)&A[base];
    __nv_bfloat16 h0 = __float2bfloat16(v.x), h1 = __float2bfloat16(v.y);
    __nv_bfloat16 h2 = __float2bfloat16(v.z), h3 = __float2bfloat16(v.w);
    __nv_bfloat16 l0 = __float2bfloat16(v.x - __bfloat162float(h0));
    __nv_bfloat16 l1 = __float2bfloat16(v.y - __bfloat162float(h1));
    __nv_bfloat16 l2 = __float2bfloat16(v.z - __bfloat162float(h2));
    __nv_bfloat16 l3 = __float2bfloat16(v.w - __bfloat162float(h3));
    __nv_bfloat162* ph = (__nv_bfloat162*)&g_A_hi[base];
    ph[0] = __nv_bfloat162(h0, h1);
    ph[1] = __nv_bfloat162(h2, h3);
    __nv_bfloat162* pl = (__nv_bfloat162*)&g_A_lo[base];
    pl[0] = __nv_bfloat162(l0, l1);
    pl[1] = __nv_bfloat162(l2, l3);
}

// ---------------- init ----------------
__global__ void init_kernel() {
    int i = blockIdx.x * blockDim.x + threadIdx.x;
    if (i < NHEADS) g_kmax[i] = -3e38f;
    if (i < NHEADS * NBF) g_kcum[i] = 0.f;
    if (i < NHEADS * HDIM * NBF) g_ctx[i] = 0.f;
    if (i < NN) g_cnt[i] = 0;
}

// ---------------- HMMA split-bf16 GEMM1: A[NN,256] @ Bt^T -> g_C1[NN,512] ----------
// CTA 128x128, 8 warps (4x2), warp 32x64. K in 4 chunks of 64, 2-stage cp.async pipe.
// smem per stage: AH|AL|BH|BL each [128 rows][64 k] bf16 (128B rows, 16B-chunk xor-swizzle)
#define HG_SMEM (2 * 65536)
__global__ __launch_bounds__(256) void hmma_gemm_kernel() {
    extern __shared__ char smem[];
    const uint32_t sb = smem_u32(smem);
    const int t = threadIdx.x;
    const int w = t >> 5;
    const int lane = t & 31;
    const int wm = w >> 1, wn = w & 1;
    const int bm = blockIdx.x * 128;
    const int bn = blockIdx.y * 128;
    const uint32_t AH = 0, AL = 16384, BH = 32768, BL = 49152;

    float acc[2][8][4];
#pragma unroll
    for (int i = 0; i < 2; i++)
#pragma unroll
        for (int j = 0; j < 8; j++)
#pragma unroll
            for (int k = 0; k < 4; k++) acc[i][j][k] = 0.f;

    const int srow = t >> 3;       // 0..31
    const int schk = t & 7;        // 16B chunk in 128B row

    // ---- prologue: stage chunk 0 into buf 0 ----
#pragma unroll
    for (int rep = 0; rep < 4; rep++) {
        int row = rep * 32 + srow;
        uint32_t so = (uint32_t)(row * 128 + ((schk ^ (row & 7)) << 4));
        bool in = (bm + row) < NN;
        uint32_t asz = in ? 16u : 0u;
        size_t ga = (size_t)(in ? (bm + row) : 0) * 256 + schk * 8;
        cp_async16(sb + AH + so, &g_A_hi[ga], asz);
        cp_async16(sb + AL + so, &g_A_lo[ga], asz);
        size_t gb = (size_t)(bn + row) * 256 + schk * 8;
        cp_async16(sb + BH + so, &g_Bt_hi[gb], 16u);
        cp_async16(sb + BL + so, &g_Bt_lo[gb], 16u);
    }
    CP_COMMIT();

    for (int c = 0; c < 4; c++) {
        if (c < 3) {
            // stage chunk c+1 into other buffer
            uint32_t base = (uint32_t)(((c + 1) & 1) * 65536);
            int k0 = (c + 1) * 64;
#pragma unroll
            for (int rep = 0; rep < 4; rep++) {
                int row = rep * 32 + srow;
                uint32_t so = base + (uint32_t)(row * 128 + ((schk ^ (row & 7)) << 4));
                bool in = (bm + row) < NN;
                uint32_t asz = in ? 16u : 0u;
                size_t ga = (size_t)(in ? (bm + row) : 0) * 256 + k0 + schk * 8;
                cp_async16(sb + AH + so, &g_A_hi[ga], asz);
                cp_async16(sb + AL + so, &g_A_lo[ga], asz);
                size_t gb = (size_t)(bn + row) * 256 + k0 + schk * 8;
                cp_async16(sb + BH + so, &g_Bt_hi[gb], 16u);
                cp_async16(sb + BL + so, &g_Bt_lo[gb], 16u);
            }
            CP_COMMIT();
            CP_WAIT1();
        } else {
            CP_WAIT0();
        }
        __syncthreads();

        const uint32_t cb = sb + (uint32_t)((c & 1) * 65536);
#pragma unroll
        for (int ks = 0; ks < 4; ks++) {
            uint32_t ah[2][4], al[2][4], bh[4][4], bl[4][4];
            int lr = lane & 15;
            int kh = lane >> 4;
            int chunk = ks * 2 + kh;
#pragma unroll
            for (int im = 0; im < 2; im++) {
                int row = wm * 32 + im * 16 + lr;
                uint32_t so = (uint32_t)(row * 128 + ((chunk ^ (row & 7)) << 4));
                LDMX4(ah[im][0], ah[im][1], ah[im][2], ah[im][3], cb + AH + so);
                LDMX4(al[im][0], al[im][1], al[im][2], al[im][3], cb + AL + so);
            }
#pragma unroll
            for (int in = 0; in < 4; in++) {
                int row = wn * 64 + in * 16 + lr;
                uint32_t so = (uint32_t)(row * 128 + ((chunk ^ (row & 7)) << 4));
                LDMX4(bh[in][0], bh[in][1], bh[in][2], bh[in][3], cb + BH + so);
                LDMX4(bl[in][0], bl[in][1], bl[in][2], bl[in][3], cb + BL + so);
            }
#pragma unroll
            for (int im = 0; im < 2; im++) {
#pragma unroll
                for (int in = 0; in < 4; in++) {
                    MMA16816(acc[im][2 * in],     ah[im], bh[in][0], bh[in][2]);
                    MMA16816(acc[im][2 * in + 1], ah[im], bh[in][1], bh[in][3]);
                    MMA16816(acc[im][2 * in],     ah[im], bl[in][0], bl[in][2]);
                    MMA16816(acc[im][2 * in + 1], ah[im], bl[in][1], bl[in][3]);
                    MMA16816(acc[im][2 * in],     al[im], bh[in][0], bh[in][2]);
                    MMA16816(acc[im][2 * in + 1], al[im], bh[in][1], bh[in][3]);
                }
            }
        }
        __syncthreads();
    }
    // ---- epilogue ----
    int gid = lane >> 2, tig = lane & 3;
#pragma unroll
    for (int im = 0; im < 2; im++) {
        int m0 = bm + wm * 32 + im * 16 + gid;
#pragma unroll
        for (int s = 0; s < 8; s++) {
            int n = bn + wn * 64 + s * 8 + tig * 2;
            float b0 = g_bias1[n], b1 = g_bias1[n + 1];
            if (m0 < NN) {
                float2 v = make_float2(acc[im][s][0] + b0, acc[im][s][1] + b1);
                *(float2*)&g_C1[(size_t)m0 * 512 + n] = v;
            }
            if (m0 + 8 < NN) {
                float2 v = make_float2(acc[im][s][2] + b0, acc[im][s][3] + b1);
                *(float2*)&g_C1[(size_t)(m0 + 8) * 512 + n] = v;
            }
        }
    }
}

// ---------------- HMMA split-bf16 GEMM2: h[NN,256] @ B2^T + elu -> g_x0[NN,64] -----
// CTA 128x64, 8 warps (4x2), warp 32x32. Single-buffered, K in 4 chunks of 64.
#define G2_SMEM (16384 * 2 + 16384)
__global__ __launch_bounds__(256) void gemm2_kernel(const float* __restrict__ bext) {
    extern __shared__ char smem[];
    const uint32_t sb = smem_u32(smem);
    const int t = threadIdx.x;
    const int w = t >> 5;
    const int lane = t & 31;
    const int wm = w >> 1, wn = w & 1;
    const int bm = blockIdx.x * 128;
    const uint32_t AH = 0, AL = 16384, BH = 32768, BL = 40960;

    float acc[2][4][4];
#pragma unroll
    for (int i = 0; i < 2; i++)
#pragma unroll
        for (int j = 0; j < 4; j++)
#pragma unroll
            for (int k = 0; k < 4; k++) acc[i][j][k] = 0.f;

    const int srow = t >> 3;
    const int schk = t & 7;
    const uint4 zero4 = make_uint4(0u, 0u, 0u, 0u);

    for (int c = 0; c < 4; c++) {
        const int k0 = c * 64;
        if (c) __syncthreads();
#pragma unroll
        for (int rep = 0; rep < 4; rep++) {
            int row = rep * 32 + srow;
            uint32_t so = (uint32_t)(row * 128 + ((schk ^ (row & 7)) << 4));
            size_t ga = (size_t)(bm + row) * 256 + k0 + schk * 8;
            bool in = (bm + row) < NN;
            *(uint4*)(smem + AH + so) = in ? *(const uint4*)&g_h_hi[ga] : zero4;
            *(uint4*)(smem + AL + so) = in ? *(const uint4*)&g_h_lo[ga] : zero4;
        }
#pragma unroll
        for (int rep = 0; rep < 2; rep++) {
            int row = rep * 32 + srow;
            uint32_t so = (uint32_t)(row * 128 + ((schk ^ (row & 7)) << 4));
            size_t gb = (size_t)row * 256 + k0 + schk * 8;
            *(uint4*)(smem + BH + so) = *(const uint4*)&g_B2_hi[gb];
            *(uint4*)(smem + BL + so) = *(const uint4*)&g_B2_lo[gb];
        }
        __syncthreads();
#pragma unroll
        for (int ks = 0; ks < 4; ks++) {
            uint32_t ah[2][4], al[2][4], bh[2][4], bl[2][4];
            int lr = lane & 15;
            int kh = lane >> 4;
            int chunk = ks * 2 + kh;
#pragma unroll
            for (int im = 0; im < 2; im++) {
                int row = wm * 32 + im * 16 + lr;
                uint32_t so = (uint32_t)(row * 128 + ((chunk ^ (row & 7)) << 4));
                LDMX4(ah[im][0], ah[im][1], ah[im][2], ah[im][3], sb + AH + so);
                LDMX4(al[im][0], al[im][1], al[im][2], al[im][3], sb + AL + so);
            }
#pragma unroll
            for (int in = 0; in < 2; in++) {
                int row = wn * 32 + in * 16 + lr;
                uint32_t so = (uint32_t)(row * 128 + ((chunk ^ (row & 7)) << 4));
                LDMX4(bh[in][0], bh[in][1], bh[in][2], bh[in][3], sb + BH + so);
                LDMX4(bl[in][0], bl[in][1], bl[in][2], bl[in][3], sb + BL + so);
            }
#pragma unroll
            for (int im = 0; im < 2; im++) {
#pragma unroll
                for (int in = 0; in < 2; in++) {
                    MMA16816(acc[im][2 * in],     ah[im], bh[in][0], bh[in][2]);
                    MMA16816(acc[im][2 * in + 1], ah[im], bh[in][1], bh[in][3]);
                    MMA16816(acc[im][2 * in],     ah[im], bl[in][0], bl[in][2]);
                    MMA16816(acc[im][2 * in + 1], ah[im], bl[in][1], bl[in][3]);
                    MMA16816(acc[im][2 * in],     al[im], bh[in][0], bh[in][2]);
                    MMA16816(acc[im][2 * in + 1], al[im], bh[in][1], bh[in][3]);
                }
            }
        }
    }
    // ---- epilogue: bias + elu ----
    int gid = lane >> 2, tig = lane & 3;
#pragma unroll
    for (int im = 0; im < 2; im++) {
        int m0 = bm + wm * 32 + im * 16 + gid;
#pragma unroll
        for (int s = 0; s < 4; s++) {
            int n = wn * 32 + s * 8 + tig * 2;
            float b0 = bext[n], b1 = bext[n + 1];
            if (m0 < NN) {
                float x = acc[im][s][0] + b0, y = acc[im][s][1] + b1;
                x = x > 0.f ? x : expm1f(x);
                y = y > 0.f ? y : expm1f(y);
                *(float2*)&g_x0[(size_t)m0 * 64 + n] = make_float2(x, y);
            }
            if (m0 + 8 < NN) {
                float x = acc[im][s][2] + b0, y = acc[im][s][3] + b1;
                x = x > 0.f ? x : expm1f(x);
                y = y > 0.f ? y : expm1f(y);
                *(float2*)&g_x0[(size_t)(m0 + 8) * 64 + n] = make_float2(x, y);
            }
        }
    }
}

// ---------------- performer: global max of dash_k per head (tiled, coalesced) ----
__global__ __launch_bounds__(256) void kmax_kernel(const float* __restrict__ proj) {
    __shared__ float ks[128][33];
    __shared__ float proj_s[NBF * HDIM];
    int t = threadIdx.x;
    int row0 = blockIdx.x * 32;
    for (int i = t; i < NBF * HDIM; i += 256) proj_s[i] = proj[i];
    for (int i = t; i < 32 * 128; i += 256) {
        int r = i >> 7, d = i & 127;
        ks[d][r] = (row0 + r < NN) ? g_C1[(size_t)(row0 + r) * 512 + 128 + d] : 0.f;
    }
    __syncthreads();
    int h = t >> 5, r = t & 31;
    float mx = -3e38f;
    if (row0 + r < NN) {
        float k[HDIM];
#pragma unroll
        for (int d = 0; d < HDIM; d++) k[d] = ks[h * HDIM + d][r] * 0.5f;
#pragma unroll
        for (int m = 0; m < NBF; m++) {
            float s = 0.f;
#pragma unroll
            for (int d = 0; d < HDIM; d++) s += k[d] * proj_s[m * HDIM + d];
            mx = fmaxf(mx, s);
        }
    }
#pragma unroll
    for (int o = 16; o > 0; o >>= 1) mx = fmaxf(mx, __shfl_xor_sync(0xffffffffu, mx, o));
    if (r == 0) atomicMaxFloat(&g_kmax[h], mx);
}

// ---------------- performer: kp features -> k_cum + context (register ctx) ----
#define KPB 224
__global__ __launch_bounds__(352) void kp_acc_kernel(const float* __restrict__ proj) {
    __shared__ float s[256][33];
    int t = threadIdx.x;
    int h = t / NBF, m = t - h * NBF;
    float pm[HDIM];
#pragma unroll
    for (int d = 0; d < HDIM; d++) pm[d] = proj[m * HDIM + d];
    float kmaxh = g_kmax[h];
    const float ratio = rsqrtf((float)NBF);
    float ctx[HDIM];
    float kc = 0.f;
#pragma unroll
    for (int d = 0; d < HDIM; d++) ctx[d] = 0.f;

    for (int tile = blockIdx.x; tile < NTILES; tile += gridDim.x) {
        int row0 = tile * 32;
        __syncthreads();
        for (int i = t; i < 32 * 256; i += 352) {
            int r = i >> 8, d = i & 255;
            s[d][r] = (row0 + r < NN) ? g_C1[(size_t)(row0 + r) * 512 + 128 + d] : 0.f;
        }
        __syncthreads();
        int rmax = min(32, NN - row0);
        for (int r = 0; r < rmax; r++) {
            float dash = 0.f, diag = 0.f;
#pragma unroll
            for (int d = 0; d < HDIM; d++) {
                float kv = s[h * HDIM + d][r] * 0.5f;
                dash += kv * pm[d];
                diag += kv * kv;
            }
            float kpv = ratio * (fexp(dash - 0.5f * diag - kmaxh) + EPSV);
            kc += kpv;
#pragma unroll
            for (int d = 0; d < HDIM; d++) ctx[d] += kpv * s[128 + h * HDIM + d][r];
        }
    }
    atomicAdd(&g_kcum[h * NBF + m], kc);
#pragma unroll
    for (int d = 0; d < HDIM; d++) atomicAdd(&g_ctx[(h * HDIM + d) * NBF + m], ctx[d]);
}

// ---------------- attention output + h = elu(concat(gnn1, trans)) as hi/lo bf16 ----
__global__ __launch_bounds__(256) void attn_kernel(const float* __restrict__ proj) {
    __shared__ float qs[128][33];
    __shared__ float proj_s[NBF * HDIM];
    __shared__ float kcum_s[NHEADS * NBF];
    __shared__ float ctx_s[NHEADS * HDIM * NBF];
    int t = threadIdx.x;
    int row0 = blockIdx.x * 32;
    for (int i = t; i < NBF * HDIM; i += 256) proj_s[i] = proj[i];
    for (int i = t; i < NHEADS * NBF; i += 256) kcum_s[i] = g_kcum[i];
    for (int i = t; i < NHEADS * HDIM * NBF; i += 256) ctx_s[i] = g_ctx[i];
    for (int i = t; i < 32 * 128; i += 256) {
        int r = i >> 7, d = i & 127;
        qs[d][r] = (row0 + r < NN) ? g_C1[(size_t)(row0 + r) * 512 + d] : 0.f;
    }
    // elu(gnn1) -> h cols [0,128), split bf16
    for (int i = t; i < 32 * 128; i += 256) {
        int r = i >> 7, d = i & 127;
        if (row0 + r < NN) {
            float v = g_C1[(size_t)(row0 + r) * 512 + 384 + d];
            v = v > 0.f ? v : expm1f(v);
            __nv_bfloat16 hi = __float2bfloat16(v);
            size_t idx = (size_t)(row0 + r) * 256 + d;
            g_h_hi[idx] = hi;
            g_h_lo[idx] = __float2bfloat16(v - __bfloat162float(hi));
        }
    }
    __syncthreads();
    int h = t >> 5, r = t & 31;
    if (row0 + r >= NN) return;
    float q[HDIM];
    float diag = 0.f;
#pragma unroll
    for (int d = 0; d < HDIM; d++) {
        q[d] = qs[h * HDIM + d][r] * 0.5f;
        diag += q[d] * q[d];
    }
    diag *= 0.5f;
    float dash[NBF];
    float qmax = -3e38f;
#pragma unroll
    for (int m = 0; m < NBF; m++) {
        float s = 0.f;
#pragma unroll
        for (int d = 0; d < HDIM; d++) s += q[d] * proj_s[m * HDIM + d];
        dash[m] = s;
        qmax = fmaxf(qmax, s);
    }
    float den = 0.f;
    float outv[HDIM];
#pragma unroll
    for (int d = 0; d < HDIM; d++) outv[d] = 0.f;
    const float ratio = rsqrtf((float)NBF);
#pragma unroll
    for (int m = 0; m < NBF; m++) {
        float qp = ratio * (fexp(dash[m] - diag - qmax) + EPSV);
        den += qp * kcum_s[h * NBF + m];
#pragma unroll
        for (int d = 0; d < HDIM; d++) outv[d] += qp * ctx_s[(h * HDIM + d) * NBF + m];
    }
    float dinv = 1.f / den;
    size_t hbase = (size_t)(row0 + r) * 256 + HIDDIM + h * HDIM;
#pragma unroll
    for (int d = 0; d < HDIM; d++) {
        float v = outv[d] * dinv;
        v = v > 0.f ? v : expm1f(v);
        __nv_bfloat16 hi = __float2bfloat16(v);
        g_h_hi[hbase + d] = hi;
        g_h_lo[hbase + d] = __float2bfloat16(v - __bfloat162float(hi));
    }
}

// ---------------- APPNP graph prep ----------------
__global__ void deg_kernel(const int* __restrict__ col) {
    int e = blockIdx.x * blockDim.x + threadIdx.x;
    if (e < NEDGE) atomicAdd(&g_cnt[col[e]], 1);
}

__global__ __launch_bounds__(1024) void scan_kernel() {
    __shared__ int wsum[32];
    __shared__ int carry_s;
    int t = threadIdx.x;
    int lane = t & 31, wid = t >> 5;
    if (t == 0) carry_s = 0;
    __syncthreads();
    for (int base = 0; base < NN; base += 1024) {
        int i = base + t;
        int v = (i < NN) ? g_cnt[i] : 0;
        int x = v;
#pragma unroll
        for (int o = 1; o < 32; o <<= 1) {
            int y = __shfl_up_sync(0xffffffffu, x, o);
            if (lane >= o) x += y;
        }
        if (lane == 31) wsum[wid] = x;
        __syncthreads();
        if (wid == 0) {
            int s = wsum[lane];
#pragma unroll
            for (int o = 1; o < 32; o <<= 1) {
                int y = __shfl_up_sync(0xffffffffu, s, o);
                if (lane >= o) s += y;
            }
            wsum[lane] = s;
        }
        __syncthreads();
        int incl = x + (wid > 0 ? wsum[wid - 1] : 0);
        int carry = carry_s;
        if (i < NN) {
            int off = carry + incl - v;
            g_off[i] = off;
            g_cursor[i] = off;
            g_dis[i] = rsqrtf((float)(v + 1));
        }
        __syncthreads();
        if (t == 1023) carry_s = carry + incl;
        __syncthreads();
    }
    if (t == 0) g_off[NN] = carry_s;
}

__global__ void fill_kernel(const int* __restrict__ row, const int* __restrict__ col) {
    int e = blockIdx.x * blockDim.x + threadIdx.x;
    if (e >= NEDGE) return;
    int r = row[e], cl = col[e];
    int pos = atomicAdd(&g_cursor[cl], 1);
    g_csr_row[pos] = r;
    g_csr_norm[pos] = g_dis[r] * g_dis[cl];
}

// ---------------- APPNP hop: warp per node, float2 per lane ----------------
template <bool LAST>
__global__ __launch_bounds__(256) void hop_kernel(int stage, float* __restrict__ out,
                                                  int out_size) {
    int node = blockIdx.x * 8 + (threadIdx.x >> 5);
    if (node >= NN) return;
    int lane = threadIdx.x & 31;
    const float* src = (stage == 0) ? g_x0 : ((stage & 1) ? g_ha : g_hb);
    float* dst = (stage & 1) ? g_hb : g_ha;
    int s = g_off[node], e = g_off[node + 1];
    float di = g_dis[node];
    float2 x0v = *(const float2*)&g_x0[(size_t)node * 64 + lane * 2];
    float2 sv = *(const float2*)&src[(size_t)node * 64 + lane * 2];
    float ax = di * di * sv.x, ay = di * di * sv.y;
    int j = s;
    for (; j + 8 <= e; j += 8) {
#pragma unroll
        for (int u = 0; u < 8; u++) {
            int r = g_csr_row[j + u];
            float wt = g_csr_norm[j + u];
            float2 v = *(const float2*)&src[(size_t)r * 64 + lane * 2];
            ax += wt * v.x;
            ay += wt * v.y;
        }
    }
    for (; j < e; j++) {
        int r = g_csr_row[j];
        float wt = g_csr_norm[j];
        float2 v = *(const float2*)&src[(size_t)r * 64 + lane * 2];
        ax += wt * v.x;
        ay += wt * v.y;
    }
    float rx = (1.f - ALPHAV) * ax + ALPHAV * x0v.x;
    float ry = (1.f - ALPHAV) * ay + ALPHAV * x0v.y;
    if (!LAST) {
        *(float2*)&dst[(size_t)node * 64 + lane * 2] = make_float2(rx, ry);
    } else {
        // fused log_softmax + output
        float mx = fmaxf(rx, ry);
#pragma unroll
        for (int o = 16; o > 0; o >>= 1) mx = fmaxf(mx, __shfl_xor_sync(0xffffffffu, mx, o));
        float ss = __expf(rx - mx) + __expf(ry - mx);
#pragma unroll
        for (int o = 16; o > 0; o >>= 1) ss += __shfl_xor_sync(0xffffffffu, ss, o);
        float lse = mx + logf(ss);
        int i0 = node * 64 + lane * 2;
        if (i0 + 1 < out_size) *(float2*)&out[i0] = make_float2(rx - lse, ry - lse);
        int j0 = NN * 64 + i0;
        if (j0 + 1 < out_size) *(float2*)&out[j0] = make_float2(rx, ry);
    }
}

// ---------------- launch ----------------
extern "C" void kernel_launch(void* const* d_in, const int* in_sizes, int n_in,
                              void* d_out, int out_size) {
    if (n_in < 13) return;
    const float* data = (const float*)d_in[0];
    const int* ei = (const int*)d_in[1];
    const float* l1w = (const float*)d_in[2];
    const float* l1b = (const float*)d_in[3];
    const float* l2w = (const float*)d_in[4];
    const float* l2b = (const float*)d_in[5];
    const float* qw = (const float*)d_in[6];
    const float* qb = (const float*)d_in[7];
    const float* kw = (const float*)d_in[8];
    const float* kb = (const float*)d_in[9];
    const float* vw = (const float*)d_in[10];
    const float* vb = (const float*)d_in[11];
    const float* proj = (const float*)d_in[12];
    const int* row = ei;
    const int* col = ei + NEDGE;

    cudaFuncSetAttribute(hmma_gemm_kernel, cudaFuncAttributeMaxDynamicSharedMemorySize, HG_SMEM);
    cudaFuncSetAttribute(gemm2_kernel, cudaFuncAttributeMaxDynamicSharedMemorySize, G2_SMEM);

    pack_kernel<<<(512 * 256 + 512 + 64 * 256 + 255) / 256, 256>>>(qw, kw, vw, l1w, qb, kb, vb, l1b, l2w);
    conv_kernel<<<(NN * 256 / 4 + 255) / 256, 256>>>(data);
    init_kernel<<<(NN + 255) / 256, 256>>>();

    dim3 g1((NN + 127) / 128, 4);
    hmma_gemm_kernel<<<g1, 256, HG_SMEM>>>();

    kmax_kernel<<<NTILES, 256>>>(proj);
    kp_acc_kernel<<<KPB, 352>>>(proj);
    attn_kernel<<<NTILES, 256>>>(proj);

    gemm2_kernel<<<(NN + 127) / 128, 256, G2_SMEM>>>(l2b);

    deg_kernel<<<(NEDGE + 255) / 256, 256>>>(col);
    scan_kernel<<<1, 1024>>>();
    fill_kernel<<<(NEDGE + 255) / 256, 256>>>(row, col);

    for (int k = 0; k < 9; k++)
        hop_kernel<false><<<(NN + 7) / 8, 256>>>(k, nullptr, 0);
    hop_kernel<true><<<(NN + 7) / 8, 256>>>(9, (float*)d_out, out_size);
}

// round 6
// speedup vs baseline: 1.9562x; 1.0834x over previous
#include <cuda_runtime.h>
#include <cuda_bf16.h>
#include <math.h>
#include <stdint.h>

// ---------------- problem constants ----------------
#define NN     50000
#define FIN    256
#define HIDDIM 128
#define NHEADS 8
#define HDIM   16
#define NCLS   64
#define NEDGE  1250000
#define NBF    44
#define EPSV   1e-4f
#define ALPHAV 0.1f

#define NTILES ((NN + 31) / 32)

// ---------------- scratch (device globals; no runtime alloc) ----------------
__device__ float g_bias1[512];
__device__ __nv_bfloat16 g_Bt_hi[512 * 256];   // [n][k] transposed packed qkv|lin1
__device__ __nv_bfloat16 g_Bt_lo[512 * 256];
__device__ __nv_bfloat16 g_B2_hi[64 * 256];    // [n][k] transposed lin2
__device__ __nv_bfloat16 g_B2_lo[64 * 256];
__device__ __nv_bfloat16 g_A_hi[(size_t)NN * 256];
__device__ __nv_bfloat16 g_A_lo[(size_t)NN * 256];
__device__ float g_C1[(size_t)NN * 512];   // per-row: q[128] | k[128] | v[128] | gnn1[128]
__device__ float g_kmax[NHEADS];
__device__ float g_kcum[NHEADS * NBF];
__device__ float g_ctx[NHEADS * HDIM * NBF];   // layout [h][d][m]
__device__ __nv_bfloat16 g_h_hi[(size_t)NN * 256];   // elu(gnn1)|elu(trans), split bf16
__device__ __nv_bfloat16 g_h_lo[(size_t)NN * 256];
__device__ float g_x0[(size_t)NN * NCLS];  // logits after lin2+elu
__device__ float g_ha[(size_t)NN * NCLS];
__device__ float g_hb[(size_t)NN * NCLS];
__device__ int   g_cnt[NN];
__device__ int   g_off[NN + 1];
__device__ int   g_cursor[NN];
__device__ float g_dis[NN];
__device__ int2  g_csr[NEDGE];            // {src row, norm as int bits}

// ---------------- PTX helpers ----------------
__device__ __forceinline__ uint32_t smem_u32(const void* p) {
    uint32_t a;
    asm("{ .reg .u64 t; cvta.to.shared.u64 t, %1; cvt.u32.u64 %0, t; }" : "=r"(a) : "l"(p));
    return a;
}
#define LDMX4(r0, r1, r2, r3, addr)                                          \
    asm volatile("ldmatrix.sync.aligned.m8n8.x4.shared.b16 {%0,%1,%2,%3}, [%4];" \
                 : "=r"(r0), "=r"(r1), "=r"(r2), "=r"(r3) : "r"(addr))
#define MMA16816(c, a, b0v, b1v)                                             \
    asm volatile("mma.sync.aligned.m16n8k16.row.col.f32.bf16.bf16.f32 "      \
                 "{%0,%1,%2,%3},{%4,%5,%6,%7},{%8,%9},{%0,%1,%2,%3};"        \
                 : "+f"((c)[0]), "+f"((c)[1]), "+f"((c)[2]), "+f"((c)[3])    \
                 : "r"((a)[0]), "r"((a)[1]), "r"((a)[2]), "r"((a)[3]),       \
                   "r"(b0v), "r"(b1v))
__device__ __forceinline__ void cp_async16(uint32_t saddr, const void* gaddr, uint32_t srcsize) {
    asm volatile("cp.async.cg.shared.global [%0], [%1], 16, %2;"
                 :: "r"(saddr), "l"(gaddr), "r"(srcsize) : "memory");
}
#define CP_COMMIT() asm volatile("cp.async.commit_group;" ::: "memory")
#define CP_WAIT0()  asm volatile("cp.async.wait_group 0;" ::: "memory")

// ---------------- misc helpers ----------------
__device__ __forceinline__ void atomicMaxFloat(float* addr, float val) {
    int* ia = (int*)addr;
    int old = *ia;
    while (__int_as_float(old) < val) {
        int assumed = old;
        old = atomicCAS(ia, assumed, __float_as_int(val));
        if (old == assumed) break;
    }
}

__device__ __forceinline__ float fexp(float x) {
    float y = fmaxf(x * 1.44269504f, -125.0f);
    float z = y + 12582912.0f;
    int   n = __float_as_int(z) - 0x4B400000;
    float f = y - (z - 12582912.0f);
    float q = 0.00133335581f;
    q = q * f + 0.00961812911f;
    q = q * f + 0.0555041087f;
    q = q * f + 0.240226507f;
    q = q * f + 0.693147181f;
    q = q * f + 1.0f;
    return q * __int_as_float((n + 127) << 23);
}

// ---------------- pack weights: bias + transposed split-bf16 B1, B2 ----------------
__global__ void pack_kernel(const float* __restrict__ qw, const float* __restrict__ kw,
                            const float* __restrict__ vw, const float* __restrict__ l1w,
                            const float* __restrict__ qb, const float* __restrict__ kb,
                            const float* __restrict__ vb, const float* __restrict__ l1b,
                            const float* __restrict__ l2w) {
    int i = blockIdx.x * blockDim.x + threadIdx.x;
    if (i < 512 * 256) {
        int n = i >> 8, k = i & 255;
        const float* src = (n < 128) ? qw : (n < 256) ? kw : (n < 384) ? vw : l1w;
        float w = src[k * 128 + (n & 127)];
        __nv_bfloat16 hi = __float2bfloat16(w);
        g_Bt_hi[i] = hi;
        g_Bt_lo[i] = __float2bfloat16(w - __bfloat162float(hi));
    } else if (i < 512 * 256 + 512) {
        int j = i - 512 * 256;
        const float* sb = (j < 128) ? qb : (j < 256) ? kb : (j < 384) ? vb : l1b;
        g_bias1[j] = sb[j & 127];
    } else if (i < 512 * 256 + 512 + 64 * 256) {
        int i2 = i - (512 * 256 + 512);
        int n = i2 >> 8, k = i2 & 255;
        float w = l2w[k * 64 + n];
        __nv_bfloat16 hi = __float2bfloat16(w);
        g_B2_hi[i2] = hi;
        g_B2_lo[i2] = __float2bfloat16(w - __bfloat162float(hi));
    }
}

// ---------------- split data to hi/lo bf16 ----------------
__global__ void conv_kernel(const float* __restrict__ A) {
    size_t i4 = (size_t)blockIdx.x * blockDim.x + threadIdx.x;
    size_t base = i4 * 4;
    if (base >= (size_t)NN * 256) return;
    float4 v = *(const float4*)&A[base];
    __nv_bfloat16 h0 = __float2bfloat16(v.x), h1 = __float2bfloat16(v.y);
    __nv_bfloat16 h2 = __float2bfloat16(v.z), h3 = __float2bfloat16(v.w);
    __nv_bfloat16 l0 = __float2bfloat16(v.x - __bfloat162float(h0));
    __nv_bfloat16 l1 = __float2bfloat16(v.y - __bfloat162float(h1));
    __nv_bfloat16 l2 = __float2bfloat16(v.z - __bfloat162float(h2));
    __nv_bfloat16 l3 = __float2bfloat16(v.w - __bfloat162float(h3));
    __nv_bfloat162* ph = (__nv_bfloat162*)&g_A_hi[base];
    ph[0] = __nv_bfloat162(h0, h1);
    ph[1] = __nv_bfloat162(h2, h3);
    __nv_bfloat162* pl = (__nv_bfloat162*)&g_A_lo[base];
    pl[0] = __nv_bfloat162(l0, l1);
    pl[1] = __nv_bfloat162(l2, l3);
}

// ---------------- init ----------------
__global__ void init_kernel() {
    int i = blockIdx.x * blockDim.x + threadIdx.x;
    if (i < NHEADS) g_kmax[i] = -3e38f;
    if (i < NHEADS * NBF) g_kcum[i] = 0.f;
    if (i < NHEADS * HDIM * NBF) g_ctx[i] = 0.f;
    if (i < NN) g_cnt[i] = 0;
}

// ---------------- HMMA split-bf16 GEMM1: A[NN,256] @ Bt^T -> g_C1[NN,512] ----------
// CTA 128x128, 8 warps (4x2), warp 32x64. K in 4 chunks of 64, single buffer + cp.async.
// smem: AH|AL|BH|BL each [128 rows][64 k] bf16 (128B rows, 16B-chunk xor-swizzle) = 64KB
#define HG_SMEM 65536
__global__ __launch_bounds__(256) void hmma_gemm_kernel() {
    extern __shared__ char smem[];
    const uint32_t sb = smem_u32(smem);
    const int t = threadIdx.x;
    const int w = t >> 5;
    const int lane = t & 31;
    const int wm = w >> 1, wn = w & 1;
    const int bm = blockIdx.x * 128;
    const int bn = blockIdx.y * 128;
    const uint32_t AH = 0, AL = 16384, BH = 32768, BL = 49152;

    float acc[2][8][4];
#pragma unroll
    for (int i = 0; i < 2; i++)
#pragma unroll
        for (int j = 0; j < 8; j++)
#pragma unroll
            for (int k = 0; k < 4; k++) acc[i][j][k] = 0.f;

    const int srow = t >> 3;       // 0..31
    const int schk = t & 7;        // 16B chunk in 128B row

    for (int c = 0; c < 4; c++) {
        const int k0 = c * 64;
        if (c) __syncthreads();
#pragma unroll
        for (int rep = 0; rep < 4; rep++) {
            int row = rep * 32 + srow;
            uint32_t so = (uint32_t)(row * 128 + ((schk ^ (row & 7)) << 4));
            bool in = (bm + row) < NN;
            uint32_t asz = in ? 16u : 0u;
            size_t ga = (size_t)(in ? (bm + row) : 0) * 256 + k0 + schk * 8;
            cp_async16(sb + AH + so, &g_A_hi[ga], asz);
            cp_async16(sb + AL + so, &g_A_lo[ga], asz);
            size_t gb = (size_t)(bn + row) * 256 + k0 + schk * 8;
            cp_async16(sb + BH + so, &g_Bt_hi[gb], 16u);
            cp_async16(sb + BL + so, &g_Bt_lo[gb], 16u);
        }
        CP_COMMIT();
        CP_WAIT0();
        __syncthreads();

#pragma unroll
        for (int ks = 0; ks < 4; ks++) {
            uint32_t ah[2][4], al[2][4], bh[4][4], bl[4][4];
            int lr = lane & 15;
            int kh = lane >> 4;
            int chunk = ks * 2 + kh;
#pragma unroll
            for (int im = 0; im < 2; im++) {
                int row = wm * 32 + im * 16 + lr;
                uint32_t so = (uint32_t)(row * 128 + ((chunk ^ (row & 7)) << 4));
                LDMX4(ah[im][0], ah[im][1], ah[im][2], ah[im][3], sb + AH + so);
                LDMX4(al[im][0], al[im][1], al[im][2], al[im][3], sb + AL + so);
            }
#pragma unroll
            for (int in = 0; in < 4; in++) {
                int row = wn * 64 + in * 16 + lr;
                uint32_t so = (uint32_t)(row * 128 + ((chunk ^ (row & 7)) << 4));
                LDMX4(bh[in][0], bh[in][1], bh[in][2], bh[in][3], sb + BH + so);
                LDMX4(bl[in][0], bl[in][1], bl[in][2], bl[in][3], sb + BL + so);
            }
#pragma unroll
            for (int im = 0; im < 2; im++) {
#pragma unroll
                for (int in = 0; in < 4; in++) {
                    MMA16816(acc[im][2 * in],     ah[im], bh[in][0], bh[in][2]);
                    MMA16816(acc[im][2 * in + 1], ah[im], bh[in][1], bh[in][3]);
                    MMA16816(acc[im][2 * in],     ah[im], bl[in][0], bl[in][2]);
                    MMA16816(acc[im][2 * in + 1], ah[im], bl[in][1], bl[in][3]);
                    MMA16816(acc[im][2 * in],     al[im], bh[in][0], bh[in][2]);
                    MMA16816(acc[im][2 * in + 1], al[im], bh[in][1], bh[in][3]);
                }
            }
        }
    }
    // ---- epilogue ----
    int gid = lane >> 2, tig = lane & 3;
#pragma unroll
    for (int im = 0; im < 2; im++) {
        int m0 = bm + wm * 32 + im * 16 + gid;
#pragma unroll
        for (int s = 0; s < 8; s++) {
            int n = bn + wn * 64 + s * 8 + tig * 2;
            float b0 = g_bias1[n], b1 = g_bias1[n + 1];
            if (m0 < NN) {
                float2 v = make_float2(acc[im][s][0] + b0, acc[im][s][1] + b1);
                *(float2*)&g_C1[(size_t)m0 * 512 + n] = v;
            }
            if (m0 + 8 < NN) {
                float2 v = make_float2(acc[im][s][2] + b0, acc[im][s][3] + b1);
                *(float2*)&g_C1[(size_t)(m0 + 8) * 512 + n] = v;
            }
        }
    }
}

// ---------------- HMMA split-bf16 GEMM2: h[NN,256] @ B2^T + elu -> g_x0[NN,64] -----
#define G2_SMEM (16384 * 2 + 16384)
__global__ __launch_bounds__(256) void gemm2_kernel(const float* __restrict__ bext) {
    extern __shared__ char smem[];
    const uint32_t sb = smem_u32(smem);
    const int t = threadIdx.x;
    const int w = t >> 5;
    const int lane = t & 31;
    const int wm = w >> 1, wn = w & 1;
    const int bm = blockIdx.x * 128;
    const uint32_t AH = 0, AL = 16384, BH = 32768, BL = 40960;

    float acc[2][4][4];
#pragma unroll
    for (int i = 0; i < 2; i++)
#pragma unroll
        for (int j = 0; j < 4; j++)
#pragma unroll
            for (int k = 0; k < 4; k++) acc[i][j][k] = 0.f;

    const int srow = t >> 3;
    const int schk = t & 7;

    for (int c = 0; c < 4; c++) {
        const int k0 = c * 64;
        if (c) __syncthreads();
#pragma unroll
        for (int rep = 0; rep < 4; rep++) {
            int row = rep * 32 + srow;
            uint32_t so = (uint32_t)(row * 128 + ((schk ^ (row & 7)) << 4));
            bool in = (bm + row) < NN;
            uint32_t asz = in ? 16u : 0u;
            size_t ga = (size_t)(in ? (bm + row) : 0) * 256 + k0 + schk * 8;
            cp_async16(sb + AH + so, &g_h_hi[ga], asz);
            cp_async16(sb + AL + so, &g_h_lo[ga], asz);
        }
#pragma unroll
        for (int rep = 0; rep < 2; rep++) {
            int row = rep * 32 + srow;
            uint32_t so = (uint32_t)(row * 128 + ((schk ^ (row & 7)) << 4));
            size_t gb = (size_t)row * 256 + k0 + schk * 8;
            cp_async16(sb + BH + so, &g_B2_hi[gb], 16u);
            cp_async16(sb + BL + so, &g_B2_lo[gb], 16u);
        }
        CP_COMMIT();
        CP_WAIT0();
        __syncthreads();
#pragma unroll
        for (int ks = 0; ks < 4; ks++) {
            uint32_t ah[2][4], al[2][4], bh[2][4], bl[2][4];
            int lr = lane & 15;
            int kh = lane >> 4;
            int chunk = ks * 2 + kh;
#pragma unroll
            for (int im = 0; im < 2; im++) {
                int row = wm * 32 + im * 16 + lr;
                uint32_t so = (uint32_t)(row * 128 + ((chunk ^ (row & 7)) << 4));
                LDMX4(ah[im][0], ah[im][1], ah[im][2], ah[im][3], sb + AH + so);
                LDMX4(al[im][0], al[im][1], al[im][2], al[im][3], sb + AL + so);
            }
#pragma unroll
            for (int in = 0; in < 2; in++) {
                int row = wn * 32 + in * 16 + lr;
                uint32_t so = (uint32_t)(row * 128 + ((chunk ^ (row & 7)) << 4));
                LDMX4(bh[in][0], bh[in][1], bh[in][2], bh[in][3], sb + BH + so);
                LDMX4(bl[in][0], bl[in][1], bl[in][2], bl[in][3], sb + BL + so);
            }
#pragma unroll
            for (int im = 0; im < 2; im++) {
#pragma unroll
                for (int in = 0; in < 2; in++) {
                    MMA16816(acc[im][2 * in],     ah[im], bh[in][0], bh[in][2]);
                    MMA16816(acc[im][2 * in + 1], ah[im], bh[in][1], bh[in][3]);
                    MMA16816(acc[im][2 * in],     ah[im], bl[in][0], bl[in][2]);
                    MMA16816(acc[im][2 * in + 1], ah[im], bl[in][1], bl[in][3]);
                    MMA16816(acc[im][2 * in],     al[im], bh[in][0], bh[in][2]);
                    MMA16816(acc[im][2 * in + 1], al[im], bh[in][1], bh[in][3]);
                }
            }
        }
    }
    // ---- epilogue: bias + elu ----
    int gid = lane >> 2, tig = lane & 3;
#pragma unroll
    for (int im = 0; im < 2; im++) {
        int m0 = bm + wm * 32 + im * 16 + gid;
#pragma unroll
        for (int s = 0; s < 4; s++) {
            int n = wn * 32 + s * 8 + tig * 2;
            float b0 = bext[n], b1 = bext[n + 1];
            if (m0 < NN) {
                float x = acc[im][s][0] + b0, y = acc[im][s][1] + b1;
                x = x > 0.f ? x : expm1f(x);
                y = y > 0.f ? y : expm1f(y);
                *(float2*)&g_x0[(size_t)m0 * 64 + n] = make_float2(x, y);
            }
            if (m0 + 8 < NN) {
                float x = acc[im][s][2] + b0, y = acc[im][s][3] + b1;
                x = x > 0.f ? x : expm1f(x);
                y = y > 0.f ? y : expm1f(y);
                *(float2*)&g_x0[(size_t)(m0 + 8) * 64 + n] = make_float2(x, y);
            }
        }
    }
}

// ---------------- performer: global max of dash_k per head (tiled, coalesced) ----
__global__ __launch_bounds__(256) void kmax_kernel(const float* __restrict__ proj) {
    __shared__ float ks[128][33];
    __shared__ float proj_s[NBF * HDIM];
    int t = threadIdx.x;
    int row0 = blockIdx.x * 32;
    for (int i = t; i < NBF * HDIM; i += 256) proj_s[i] = proj[i];
    for (int i = t; i < 32 * 128; i += 256) {
        int r = i >> 7, d = i & 127;
        ks[d][r] = (row0 + r < NN) ? g_C1[(size_t)(row0 + r) * 512 + 128 + d] : 0.f;
    }
    __syncthreads();
    int h = t >> 5, r = t & 31;
    float mx = -3e38f;
    if (row0 + r < NN) {
        float k[HDIM];
#pragma unroll
        for (int d = 0; d < HDIM; d++) k[d] = ks[h * HDIM + d][r] * 0.5f;
#pragma unroll
        for (int m = 0; m < NBF; m++) {
            float s = 0.f;
#pragma unroll
            for (int d = 0; d < HDIM; d++) s += k[d] * proj_s[m * HDIM + d];
            mx = fmaxf(mx, s);
        }
    }
#pragma unroll
    for (int o = 16; o > 0; o >>= 1) mx = fmaxf(mx, __shfl_xor_sync(0xffffffffu, mx, o));
    if (r == 0) atomicMaxFloat(&g_kmax[h], mx);
}

// ---------------- performer: kp features -> k_cum + context (register ctx) ----
#define KPB 224
__global__ __launch_bounds__(352) void kp_acc_kernel(const float* __restrict__ proj) {
    __shared__ float s[256][33];
    int t = threadIdx.x;
    int h = t / NBF, m = t - h * NBF;
    float pm[HDIM];
#pragma unroll
    for (int d = 0; d < HDIM; d++) pm[d] = proj[m * HDIM + d];
    float kmaxh = g_kmax[h];
    const float ratio = rsqrtf((float)NBF);
    float ctx[HDIM];
    float kc = 0.f;
#pragma unroll
    for (int d = 0; d < HDIM; d++) ctx[d] = 0.f;

    for (int tile = blockIdx.x; tile < NTILES; tile += gridDim.x) {
        int row0 = tile * 32;
        __syncthreads();
        for (int i = t; i < 32 * 256; i += 352) {
            int r = i >> 8, d = i & 255;
            s[d][r] = (row0 + r < NN) ? g_C1[(size_t)(row0 + r) * 512 + 128 + d] : 0.f;
        }
        __syncthreads();
        int rmax = min(32, NN - row0);
        for (int r = 0; r < rmax; r++) {
            float dash = 0.f, diag = 0.f;
#pragma unroll
            for (int d = 0; d < HDIM; d++) {
                float kv = s[h * HDIM + d][r] * 0.5f;
                dash += kv * pm[d];
                diag += kv * kv;
            }
            float kpv = ratio * (fexp(dash - 0.5f * diag - kmaxh) + EPSV);
            kc += kpv;
#pragma unroll
            for (int d = 0; d < HDIM; d++) ctx[d] += kpv * s[128 + h * HDIM + d][r];
        }
    }
    atomicAdd(&g_kcum[h * NBF + m], kc);
#pragma unroll
    for (int d = 0; d < HDIM; d++) atomicAdd(&g_ctx[(h * HDIM + d) * NBF + m], ctx[d]);
}

// ---------------- attention output + h = elu(concat(gnn1, trans)) as hi/lo bf16 ----
__global__ __launch_bounds__(256) void attn_kernel(const float* __restrict__ proj) {
    __shared__ float qs[128][33];
    __shared__ float proj_s[NBF * HDIM];
    __shared__ float kcum_s[NHEADS * NBF];
    __shared__ float ctx_s[NHEADS * HDIM * NBF];
    int t = threadIdx.x;
    int row0 = blockIdx.x * 32;
    for (int i = t; i < NBF * HDIM; i += 256) proj_s[i] = proj[i];
    for (int i = t; i < NHEADS * NBF; i += 256) kcum_s[i] = g_kcum[i];
    for (int i = t; i < NHEADS * HDIM * NBF; i += 256) ctx_s[i] = g_ctx[i];
    for (int i = t; i < 32 * 128; i += 256) {
        int r = i >> 7, d = i & 127;
        qs[d][r] = (row0 + r < NN) ? g_C1[(size_t)(row0 + r) * 512 + d] : 0.f;
    }
    // elu(gnn1) -> h cols [0,128), split bf16, paired loads/stores
    for (int i = t; i < 32 * 64; i += 256) {
        int r = i >> 6, dp = (i & 63) * 2;
        if (row0 + r < NN) {
            float2 v = *(const float2*)&g_C1[(size_t)(row0 + r) * 512 + 384 + dp];
            v.x = v.x > 0.f ? v.x : expm1f(v.x);
            v.y = v.y > 0.f ? v.y : expm1f(v.y);
            __nv_bfloat16 hx = __float2bfloat16(v.x), hy = __float2bfloat16(v.y);
            size_t idx = (size_t)(row0 + r) * 256 + dp;
            *(__nv_bfloat162*)&g_h_hi[idx] = __nv_bfloat162(hx, hy);
            *(__nv_bfloat162*)&g_h_lo[idx] =
                __nv_bfloat162(__float2bfloat16(v.x - __bfloat162float(hx)),
                               __float2bfloat16(v.y - __bfloat162float(hy)));
        }
    }
    __syncthreads();
    int h = t >> 5, r = t & 31;
    if (row0 + r >= NN) return;
    float q[HDIM];
    float diag = 0.f;
#pragma unroll
    for (int d = 0; d < HDIM; d++) {
        q[d] = qs[h * HDIM + d][r] * 0.5f;
        diag += q[d] * q[d];
    }
    diag *= 0.5f;
    float dash[NBF];
    float qmax = -3e38f;
#pragma unroll
    for (int m = 0; m < NBF; m++) {
        float s = 0.f;
#pragma unroll
        for (int d = 0; d < HDIM; d++) s += q[d] * proj_s[m * HDIM + d];
        dash[m] = s;
        qmax = fmaxf(qmax, s);
    }
    float den = 0.f;
    float outv[HDIM];
#pragma unroll
    for (int d = 0; d < HDIM; d++) outv[d] = 0.f;
    const float ratio = rsqrtf((float)NBF);
#pragma unroll
    for (int m = 0; m < NBF; m++) {
        float qp = ratio * (fexp(dash[m] - diag - qmax) + EPSV);
        den += qp * kcum_s[h * NBF + m];
#pragma unroll
        for (int d = 0; d < HDIM; d++) outv[d] += qp * ctx_s[(h * HDIM + d) * NBF + m];
    }
    float dinv = 1.f / den;
    size_t hbase = (size_t)(row0 + r) * 256 + HIDDIM + h * HDIM;
#pragma unroll
    for (int d = 0; d < HDIM; d += 2) {
        float x = outv[d] * dinv, y = outv[d + 1] * dinv;
        x = x > 0.f ? x : expm1f(x);
        y = y > 0.f ? y : expm1f(y);
        __nv_bfloat16 hx = __float2bfloat16(x), hy = __float2bfloat16(y);
        *(__nv_bfloat162*)&g_h_hi[hbase + d] = __nv_bfloat162(hx, hy);
        *(__nv_bfloat162*)&g_h_lo[hbase + d] =
            __nv_bfloat162(__float2bfloat16(x - __bfloat162float(hx)),
                           __float2bfloat16(y - __bfloat162float(hy)));
    }
}

// ---------------- APPNP graph prep ----------------
__global__ void deg_kernel(const int* __restrict__ col) {
    int e = blockIdx.x * blockDim.x + threadIdx.x;
    if (e < NEDGE) atomicAdd(&g_cnt[col[e]], 1);
}

__global__ __launch_bounds__(1024) void scan_kernel() {
    __shared__ int wsum[32];
    __shared__ int carry_s;
    int t = threadIdx.x;
    int lane = t & 31, wid = t >> 5;
    if (t == 0) carry_s = 0;
    __syncthreads();
    for (int base = 0; base < NN; base += 1024) {
        int i = base + t;
        int v = (i < NN) ? g_cnt[i] : 0;
        int x = v;
#pragma unroll
        for (int o = 1; o < 32; o <<= 1) {
            int y = __shfl_up_sync(0xffffffffu, x, o);
            if (lane >= o) x += y;
        }
        if (lane == 31) wsum[wid] = x;
        __syncthreads();
        if (wid == 0) {
            int s = wsum[lane];
#pragma unroll
            for (int o = 1; o < 32; o <<= 1) {
                int y = __shfl_up_sync(0xffffffffu, s, o);
                if (lane >= o) s += y;
            }
            wsum[lane] = s;
        }
        __syncthreads();
        int incl = x + (wid > 0 ? wsum[wid - 1] : 0);
        int carry = carry_s;
        if (i < NN) {
            int off = carry + incl - v;
            g_off[i] = off;
            g_cursor[i] = off;
            g_dis[i] = rsqrtf((float)(v + 1));
        }
        __syncthreads();
        if (t == 1023) carry_s = carry + incl;
        __syncthreads();
    }
    if (t == 0) g_off[NN] = carry_s;
}

__global__ void fill_kernel(const int* __restrict__ row, const int* __restrict__ col) {
    int e = blockIdx.x * blockDim.x + threadIdx.x;
    if (e >= NEDGE) return;
    int r = row[e], cl = col[e];
    int pos = atomicAdd(&g_cursor[cl], 1);
    g_csr[pos] = make_int2(r, __float_as_int(g_dis[r] * g_dis[cl]));
}

// ---------------- APPNP hop: warp per node, float2 per lane ----------------
template <bool LAST>
__global__ __launch_bounds__(256) void hop_kernel(int stage, float* __restrict__ out,
                                                  int out_size) {
    int node = blockIdx.x * 8 + (threadIdx.x >> 5);
    if (node >= NN) return;
    int lane = threadIdx.x & 31;
    const float* src = (stage == 0) ? g_x0 : ((stage & 1) ? g_ha : g_hb);
    float* dst = (stage & 1) ? g_hb : g_ha;
    int s = g_off[node], e = g_off[node + 1];
    float di = g_dis[node];
    float2 x0v = *(const float2*)&g_x0[(size_t)node * 64 + lane * 2];
    float2 sv = *(const float2*)&src[(size_t)node * 64 + lane * 2];
    float ax = di * di * sv.x, ay = di * di * sv.y;
    int j = s;
    for (; j + 8 <= e; j += 8) {
#pragma unroll
        for (int u = 0; u < 8; u++) {
            int2 ce = g_csr[j + u];
            float wt = __int_as_float(ce.y);
            float2 v = *(const float2*)&src[(size_t)ce.x * 64 + lane * 2];
            ax += wt * v.x;
            ay += wt * v.y;
        }
    }
    for (; j < e; j++) {
        int2 ce = g_csr[j];
        float wt = __int_as_float(ce.y);
        float2 v = *(const float2*)&src[(size_t)ce.x * 64 + lane * 2];
        ax += wt * v.x;
        ay += wt * v.y;
    }
    float rx = (1.f - ALPHAV) * ax + ALPHAV * x0v.x;
    float ry = (1.f - ALPHAV) * ay + ALPHAV * x0v.y;
    if (!LAST) {
        *(float2*)&dst[(size_t)node * 64 + lane * 2] = make_float2(rx, ry);
    } else {
        float mx = fmaxf(rx, ry);
#pragma unroll
        for (int o = 16; o > 0; o >>= 1) mx = fmaxf(mx, __shfl_xor_sync(0xffffffffu, mx, o));
        float ss = __expf(rx - mx) + __expf(ry - mx);
#pragma unroll
        for (int o = 16; o > 0; o >>= 1) ss += __shfl_xor_sync(0xffffffffu, ss, o);
        float lse = mx + logf(ss);
        int i0 = node * 64 + lane * 2;
        if (i0 + 1 < out_size) *(float2*)&out[i0] = make_float2(rx - lse, ry - lse);
        int j0 = NN * 64 + i0;
        if (j0 + 1 < out_size) *(float2*)&out[j0] = make_float2(rx, ry);
    }
}

// ---------------- launch ----------------
extern "C" void kernel_launch(void* const* d_in, const int* in_sizes, int n_in,
                              void* d_out, int out_size) {
    if (n_in < 13) return;
    const float* data = (const float*)d_in[0];
    const int* ei = (const int*)d_in[1];
    const float* l1w = (const float*)d_in[2];
    const float* l1b = (const float*)d_in[3];
    const float* l2w = (const float*)d_in[4];
    const float* l2b = (const float*)d_in[5];
    const float* qw = (const float*)d_in[6];
    const float* qb = (const float*)d_in[7];
    const float* kw = (const float*)d_in[8];
    const float* kb = (const float*)d_in[9];
    const float* vw = (const float*)d_in[10];
    const float* vb = (const float*)d_in[11];
    const float* proj = (const float*)d_in[12];
    const int* row = ei;
    const int* col = ei + NEDGE;

    cudaFuncSetAttribute(hmma_gemm_kernel, cudaFuncAttributeMaxDynamicSharedMemorySize, HG_SMEM);
    cudaFuncSetAttribute(gemm2_kernel, cudaFuncAttributeMaxDynamicSharedMemorySize, G2_SMEM);

    pack_kernel<<<(512 * 256 + 512 + 64 * 256 + 255) / 256, 256>>>(qw, kw, vw, l1w, qb, kb, vb, l1b, l2w);
    conv_kernel<<<(NN * 256 / 4 + 255) / 256, 256>>>(data);
    init_kernel<<<(NN + 255) / 256, 256>>>();

    dim3 g1((NN + 127) / 128, 4);
    hmma_gemm_kernel<<<g1, 256, HG_SMEM>>>();

    kmax_kernel<<<NTILES, 256>>>(proj);
    kp_acc_kernel<<<KPB, 352>>>(proj);
    attn_kernel<<<NTILES, 256>>>(proj);

    gemm2_kernel<<<(NN + 127) / 128, 256, G2_SMEM>>>(l2b);

    deg_kernel<<<(NEDGE + 255) / 256, 256>>>(col);
    scan_kernel<<<1, 1024>>>();
    fill_kernel<<<(NEDGE + 255) / 256, 256>>>(row, col);

    for (int k = 0; k < 9; k++)
        hop_kernel<false><<<(NN + 7) / 8, 256>>>(k, nullptr, 0);
    hop_kernel<true><<<(NN + 7) / 8, 256>>>(9, (float*)d_out, out_size);
}

// round 7
// speedup vs baseline: 1.9707x; 1.0074x over previous
#include <cuda_runtime.h>
#include <cuda_bf16.h>
#include <cuda_fp16.h>
#include <math.h>
#include <stdint.h>

// ---------------- problem constants ----------------
#define NN     50000
#define FIN    256
#define HIDDIM 128
#define NHEADS 8
#define HDIM   16
#define NCLS   64
#define NEDGE  1250000
#define NBF    44
#define EPSV   1e-4f
#define ALPHAV 0.1f

#define NTILES ((NN + 31) / 32)

// ---------------- scratch (device globals; no runtime alloc) ----------------
__device__ float g_bias1[512];
__device__ __nv_bfloat16 g_Bt_hi[512 * 256];   // [n][k] transposed packed qkv|lin1
__device__ __nv_bfloat16 g_Bt_lo[512 * 256];
__device__ __nv_bfloat16 g_B2_hi[64 * 256];    // [n][k] transposed lin2
__device__ __nv_bfloat16 g_B2_lo[64 * 256];
__device__ __nv_bfloat16 g_A_hi[(size_t)NN * 256];
__device__ __nv_bfloat16 g_A_lo[(size_t)NN * 256];
__device__ float g_C1[(size_t)NN * 512];   // per-row: q[128] | k[128] | v[128] | gnn1[128]
__device__ float g_kmax[NHEADS];
__device__ float g_kcum[NHEADS * NBF];
__device__ float g_ctx[NHEADS * HDIM * NBF];   // layout [h][d][m]
__device__ __nv_bfloat16 g_h_hi[(size_t)NN * 256];   // elu(gnn1)|elu(trans), split bf16
__device__ __nv_bfloat16 g_h_lo[(size_t)NN * 256];
__device__ float  g_x0[(size_t)NN * NCLS]; // logits after lin2+elu (fp32, alpha term)
__device__ __half g_x0h[(size_t)NN * NCLS];// fp16 copy for gathering
__device__ __half g_ha[(size_t)NN * NCLS]; // fp16 hop intermediates
__device__ __half g_hb[(size_t)NN * NCLS];
__device__ int   g_cnt[NN];
__device__ int   g_off[NN + 1];
__device__ int   g_cursor[NN];
__device__ float g_dis[NN];
__device__ int2  g_csr[NEDGE];            // {src row, norm as int bits}

// ---------------- PTX helpers ----------------
__device__ __forceinline__ uint32_t smem_u32(const void* p) {
    uint32_t a;
    asm("{ .reg .u64 t; cvta.to.shared.u64 t, %1; cvt.u32.u64 %0, t; }" : "=r"(a) : "l"(p));
    return a;
}
#define LDMX4(r0, r1, r2, r3, addr)                                          \
    asm volatile("ldmatrix.sync.aligned.m8n8.x4.shared.b16 {%0,%1,%2,%3}, [%4];" \
                 : "=r"(r0), "=r"(r1), "=r"(r2), "=r"(r3) : "r"(addr))
#define MMA16816(c, a, b0v, b1v)                                             \
    asm volatile("mma.sync.aligned.m16n8k16.row.col.f32.bf16.bf16.f32 "      \
                 "{%0,%1,%2,%3},{%4,%5,%6,%7},{%8,%9},{%0,%1,%2,%3};"        \
                 : "+f"((c)[0]), "+f"((c)[1]), "+f"((c)[2]), "+f"((c)[3])    \
                 : "r"((a)[0]), "r"((a)[1]), "r"((a)[2]), "r"((a)[3]),       \
                   "r"(b0v), "r"(b1v))
__device__ __forceinline__ void cp_async16(uint32_t saddr, const void* gaddr, uint32_t srcsize) {
    asm volatile("cp.async.cg.shared.global [%0], [%1], 16, %2;"
                 :: "r"(saddr), "l"(gaddr), "r"(srcsize) : "memory");
}
#define CP_COMMIT() asm volatile("cp.async.commit_group;" ::: "memory")
#define CP_WAIT0()  asm volatile("cp.async.wait_group 0;" ::: "memory")

// ---------------- misc helpers ----------------
__device__ __forceinline__ void atomicMaxFloat(float* addr, float val) {
    int* ia = (int*)addr;
    int old = *ia;
    while (__int_as_float(old) < val) {
        int assumed = old;
        old = atomicCAS(ia, assumed, __float_as_int(val));
        if (old == assumed) break;
    }
}

__device__ __forceinline__ float fexp(float x) {
    float y = fmaxf(x * 1.44269504f, -125.0f);
    float z = y + 12582912.0f;
    int   n = __float_as_int(z) - 0x4B400000;
    float f = y - (z - 12582912.0f);
    float q = 0.00133335581f;
    q = q * f + 0.00961812911f;
    q = q * f + 0.0555041087f;
    q = q * f + 0.240226507f;
    q = q * f + 0.693147181f;
    q = q * f + 1.0f;
    return q * __int_as_float((n + 127) << 23);
}

// ---------------- pack weights: bias + transposed split-bf16 B1, B2 ----------------
__global__ void pack_kernel(const float* __restrict__ qw, const float* __restrict__ kw,
                            const float* __restrict__ vw, const float* __restrict__ l1w,
                            const float* __restrict__ qb, const float* __restrict__ kb,
                            const float* __restrict__ vb, const float* __restrict__ l1b,
                            const float* __restrict__ l2w) {
    int i = blockIdx.x * blockDim.x + threadIdx.x;
    if (i < 512 * 256) {
        int n = i >> 8, k = i & 255;
        const float* src = (n < 128) ? qw : (n < 256) ? kw : (n < 384) ? vw : l1w;
        float w = src[k * 128 + (n & 127)];
        __nv_bfloat16 hi = __float2bfloat16(w);
        g_Bt_hi[i] = hi;
        g_Bt_lo[i] = __float2bfloat16(w - __bfloat162float(hi));
    } else if (i < 512 * 256 + 512) {
        int j = i - 512 * 256;
        const float* sb = (j < 128) ? qb : (j < 256) ? kb : (j < 384) ? vb : l1b;
        g_bias1[j] = sb[j & 127];
    } else if (i < 512 * 256 + 512 + 64 * 256) {
        int i2 = i - (512 * 256 + 512);
        int n = i2 >> 8, k = i2 & 255;
        float w = l2w[k * 64 + n];
        __nv_bfloat16 hi = __float2bfloat16(w);
        g_B2_hi[i2] = hi;
        g_B2_lo[i2] = __float2bfloat16(w - __bfloat162float(hi));
    }
}

// ---------------- split data to hi/lo bf16 ----------------
__global__ void conv_kernel(const float* __restrict__ A) {
    size_t i4 = (size_t)blockIdx.x * blockDim.x + threadIdx.x;
    size_t base = i4 * 4;
    if (base >= (size_t)NN * 256) return;
    float4 v = *(const float4*)&A[base];
    __nv_bfloat16 h0 = __float2bfloat16(v.x), h1 = __float2bfloat16(v.y);
    __nv_bfloat16 h2 = __float2bfloat16(v.z), h3 = __float2bfloat16(v.w);
    __nv_bfloat16 l0 = __float2bfloat16(v.x - __bfloat162float(h0));
    __nv_bfloat16 l1 = __float2bfloat16(v.y - __bfloat162float(h1));
    __nv_bfloat16 l2 = __float2bfloat16(v.z - __bfloat162float(h2));
    __nv_bfloat16 l3 = __float2bfloat16(v.w - __bfloat162float(h3));
    __nv_bfloat162* ph = (__nv_bfloat162*)&g_A_hi[base];
    ph[0] = __nv_bfloat162(h0, h1);
    ph[1] = __nv_bfloat162(h2, h3);
    __nv_bfloat162* pl = (__nv_bfloat162*)&g_A_lo[base];
    pl[0] = __nv_bfloat162(l0, l1);
    pl[1] = __nv_bfloat162(l2, l3);
}

// ---------------- init ----------------
__global__ void init_kernel() {
    int i = blockIdx.x * blockDim.x + threadIdx.x;
    if (i < NHEADS) g_kmax[i] = -3e38f;
    if (i < NHEADS * NBF) g_kcum[i] = 0.f;
    if (i < NHEADS * HDIM * NBF) g_ctx[i] = 0.f;
    if (i < NN) g_cnt[i] = 0;
}

// ---------------- HMMA split-bf16 GEMM1: A[NN,256] @ Bt^T -> g_C1[NN,512] ----------
#define HG_SMEM 65536
__global__ __launch_bounds__(256) void hmma_gemm_kernel() {
    extern __shared__ char smem[];
    const uint32_t sb = smem_u32(smem);
    const int t = threadIdx.x;
    const int w = t >> 5;
    const int lane = t & 31;
    const int wm = w >> 1, wn = w & 1;
    const int bm = blockIdx.x * 128;
    const int bn = blockIdx.y * 128;
    const uint32_t AH = 0, AL = 16384, BH = 32768, BL = 49152;

    float acc[2][8][4];
#pragma unroll
    for (int i = 0; i < 2; i++)
#pragma unroll
        for (int j = 0; j < 8; j++)
#pragma unroll
            for (int k = 0; k < 4; k++) acc[i][j][k] = 0.f;

    const int srow = t >> 3;
    const int schk = t & 7;

    for (int c = 0; c < 4; c++) {
        const int k0 = c * 64;
        if (c) __syncthreads();
#pragma unroll
        for (int rep = 0; rep < 4; rep++) {
            int row = rep * 32 + srow;
            uint32_t so = (uint32_t)(row * 128 + ((schk ^ (row & 7)) << 4));
            bool in = (bm + row) < NN;
            uint32_t asz = in ? 16u : 0u;
            size_t ga = (size_t)(in ? (bm + row) : 0) * 256 + k0 + schk * 8;
            cp_async16(sb + AH + so, &g_A_hi[ga], asz);
            cp_async16(sb + AL + so, &g_A_lo[ga], asz);
            size_t gb = (size_t)(bn + row) * 256 + k0 + schk * 8;
            cp_async16(sb + BH + so, &g_Bt_hi[gb], 16u);
            cp_async16(sb + BL + so, &g_Bt_lo[gb], 16u);
        }
        CP_COMMIT();
        CP_WAIT0();
        __syncthreads();

#pragma unroll
        for (int ks = 0; ks < 4; ks++) {
            uint32_t ah[2][4], al[2][4], bh[4][4], bl[4][4];
            int lr = lane & 15;
            int kh = lane >> 4;
            int chunk = ks * 2 + kh;
#pragma unroll
            for (int im = 0; im < 2; im++) {
                int row = wm * 32 + im * 16 + lr;
                uint32_t so = (uint32_t)(row * 128 + ((chunk ^ (row & 7)) << 4));
                LDMX4(ah[im][0], ah[im][1], ah[im][2], ah[im][3], sb + AH + so);
                LDMX4(al[im][0], al[im][1], al[im][2], al[im][3], sb + AL + so);
            }
#pragma unroll
            for (int in = 0; in < 4; in++) {
                int row = wn * 64 + in * 16 + lr;
                uint32_t so = (uint32_t)(row * 128 + ((chunk ^ (row & 7)) << 4));
                LDMX4(bh[in][0], bh[in][1], bh[in][2], bh[in][3], sb + BH + so);
                LDMX4(bl[in][0], bl[in][1], bl[in][2], bl[in][3], sb + BL + so);
            }
#pragma unroll
            for (int im = 0; im < 2; im++) {
#pragma unroll
                for (int in = 0; in < 4; in++) {
                    MMA16816(acc[im][2 * in],     ah[im], bh[in][0], bh[in][2]);
                    MMA16816(acc[im][2 * in + 1], ah[im], bh[in][1], bh[in][3]);
                    MMA16816(acc[im][2 * in],     ah[im], bl[in][0], bl[in][2]);
                    MMA16816(acc[im][2 * in + 1], ah[im], bl[in][1], bl[in][3]);
                    MMA16816(acc[im][2 * in],     al[im], bh[in][0], bh[in][2]);
                    MMA16816(acc[im][2 * in + 1], al[im], bh[in][1], bh[in][3]);
                }
            }
        }
    }
    // ---- epilogue ----
    int gid = lane >> 2, tig = lane & 3;
#pragma unroll
    for (int im = 0; im < 2; im++) {
        int m0 = bm + wm * 32 + im * 16 + gid;
#pragma unroll
        for (int s = 0; s < 8; s++) {
            int n = bn + wn * 64 + s * 8 + tig * 2;
            float b0 = g_bias1[n], b1 = g_bias1[n + 1];
            if (m0 < NN) {
                float2 v = make_float2(acc[im][s][0] + b0, acc[im][s][1] + b1);
                *(float2*)&g_C1[(size_t)m0 * 512 + n] = v;
            }
            if (m0 + 8 < NN) {
                float2 v = make_float2(acc[im][s][2] + b0, acc[im][s][3] + b1);
                *(float2*)&g_C1[(size_t)(m0 + 8) * 512 + n] = v;
            }
        }
    }
}

// ---------------- HMMA split-bf16 GEMM2: h[NN,256] @ B2^T + elu -> g_x0 (+fp16 copy) --
#define G2_SMEM (16384 * 2 + 16384)
__global__ __launch_bounds__(256) void gemm2_kernel(const float* __restrict__ bext) {
    extern __shared__ char smem[];
    const uint32_t sb = smem_u32(smem);
    const int t = threadIdx.x;
    const int w = t >> 5;
    const int lane = t & 31;
    const int wm = w >> 1, wn = w & 1;
    const int bm = blockIdx.x * 128;
    const uint32_t AH = 0, AL = 16384, BH = 32768, BL = 40960;

    float acc[2][4][4];
#pragma unroll
    for (int i = 0; i < 2; i++)
#pragma unroll
        for (int j = 0; j < 4; j++)
#pragma unroll
            for (int k = 0; k < 4; k++) acc[i][j][k] = 0.f;

    const int srow = t >> 3;
    const int schk = t & 7;

    for (int c = 0; c < 4; c++) {
        const int k0 = c * 64;
        if (c) __syncthreads();
#pragma unroll
        for (int rep = 0; rep < 4; rep++) {
            int row = rep * 32 + srow;
            uint32_t so = (uint32_t)(row * 128 + ((schk ^ (row & 7)) << 4));
            bool in = (bm + row) < NN;
            uint32_t asz = in ? 16u : 0u;
            size_t ga = (size_t)(in ? (bm + row) : 0) * 256 + k0 + schk * 8;
            cp_async16(sb + AH + so, &g_h_hi[ga], asz);
            cp_async16(sb + AL + so, &g_h_lo[ga], asz);
        }
#pragma unroll
        for (int rep = 0; rep < 2; rep++) {
            int row = rep * 32 + srow;
            uint32_t so = (uint32_t)(row * 128 + ((schk ^ (row & 7)) << 4));
            size_t gb = (size_t)row * 256 + k0 + schk * 8;
            cp_async16(sb + BH + so, &g_B2_hi[gb], 16u);
            cp_async16(sb + BL + so, &g_B2_lo[gb], 16u);
        }
        CP_COMMIT();
        CP_WAIT0();
        __syncthreads();
#pragma unroll
        for (int ks = 0; ks < 4; ks++) {
            uint32_t ah[2][4], al[2][4], bh[2][4], bl[2][4];
            int lr = lane & 15;
            int kh = lane >> 4;
            int chunk = ks * 2 + kh;
#pragma unroll
            for (int im = 0; im < 2; im++) {
                int row = wm * 32 + im * 16 + lr;
                uint32_t so = (uint32_t)(row * 128 + ((chunk ^ (row & 7)) << 4));
                LDMX4(ah[im][0], ah[im][1], ah[im][2], ah[im][3], sb + AH + so);
                LDMX4(al[im][0], al[im][1], al[im][2], al[im][3], sb + AL + so);
            }
#pragma unroll
            for (int in = 0; in < 2; in++) {
                int row = wn * 32 + in * 16 + lr;
                uint32_t so = (uint32_t)(row * 128 + ((chunk ^ (row & 7)) << 4));
                LDMX4(bh[in][0], bh[in][1], bh[in][2], bh[in][3], sb + BH + so);
                LDMX4(bl[in][0], bl[in][1], bl[in][2], bl[in][3], sb + BL + so);
            }
#pragma unroll
            for (int im = 0; im < 2; im++) {
#pragma unroll
                for (int in = 0; in < 2; in++) {
                    MMA16816(acc[im][2 * in],     ah[im], bh[in][0], bh[in][2]);
                    MMA16816(acc[im][2 * in + 1], ah[im], bh[in][1], bh[in][3]);
                    MMA16816(acc[im][2 * in],     ah[im], bl[in][0], bl[in][2]);
                    MMA16816(acc[im][2 * in + 1], ah[im], bl[in][1], bl[in][3]);
                    MMA16816(acc[im][2 * in],     al[im], bh[in][0], bh[in][2]);
                    MMA16816(acc[im][2 * in + 1], al[im], bh[in][1], bh[in][3]);
                }
            }
        }
    }
    // ---- epilogue: bias + elu, fp32 + fp16 copy ----
    int gid = lane >> 2, tig = lane & 3;
#pragma unroll
    for (int im = 0; im < 2; im++) {
        int m0 = bm + wm * 32 + im * 16 + gid;
#pragma unroll
        for (int s = 0; s < 4; s++) {
            int n = wn * 32 + s * 8 + tig * 2;
            float b0 = bext[n], b1 = bext[n + 1];
            if (m0 < NN) {
                float x = acc[im][s][0] + b0, y = acc[im][s][1] + b1;
                x = x > 0.f ? x : expm1f(x);
                y = y > 0.f ? y : expm1f(y);
                *(float2*)&g_x0[(size_t)m0 * 64 + n] = make_float2(x, y);
                *(__half2*)&g_x0h[(size_t)m0 * 64 + n] = __floats2half2_rn(x, y);
            }
            if (m0 + 8 < NN) {
                float x = acc[im][s][2] + b0, y = acc[im][s][3] + b1;
                x = x > 0.f ? x : expm1f(x);
                y = y > 0.f ? y : expm1f(y);
                *(float2*)&g_x0[(size_t)(m0 + 8) * 64 + n] = make_float2(x, y);
                *(__half2*)&g_x0h[(size_t)(m0 + 8) * 64 + n] = __floats2half2_rn(x, y);
            }
        }
    }
}

// ---------------- performer: global max of dash_k per head (tiled, coalesced) ----
__global__ __launch_bounds__(256) void kmax_kernel(const float* __restrict__ proj) {
    __shared__ float ks[128][33];
    __shared__ float proj_s[NBF * HDIM];
    int t = threadIdx.x;
    int row0 = blockIdx.x * 32;
    for (int i = t; i < NBF * HDIM; i += 256) proj_s[i] = proj[i];
    for (int i = t; i < 32 * 128; i += 256) {
        int r = i >> 7, d = i & 127;
        ks[d][r] = (row0 + r < NN) ? g_C1[(size_t)(row0 + r) * 512 + 128 + d] : 0.f;
    }
    __syncthreads();
    int h = t >> 5, r = t & 31;
    float mx = -3e38f;
    if (row0 + r < NN) {
        float k[HDIM];
#pragma unroll
        for (int d = 0; d < HDIM; d++) k[d] = ks[h * HDIM + d][r] * 0.5f;
#pragma unroll
        for (int m = 0; m < NBF; m++) {
            float s = 0.f;
#pragma unroll
            for (int d = 0; d < HDIM; d++) s += k[d] * proj_s[m * HDIM + d];
            mx = fmaxf(mx, s);
        }
    }
#pragma unroll
    for (int o = 16; o > 0; o >>= 1) mx = fmaxf(mx, __shfl_xor_sync(0xffffffffu, mx, o));
    if (r == 0) atomicMaxFloat(&g_kmax[h], mx);
}

// ---------------- performer: kp features -> k_cum + context (register ctx) ----
#define KPB 224
__global__ __launch_bounds__(352) void kp_acc_kernel(const float* __restrict__ proj) {
    __shared__ float s[256][33];
    int t = threadIdx.x;
    int h = t / NBF, m = t - h * NBF;
    float pm[HDIM];
#pragma unroll
    for (int d = 0; d < HDIM; d++) pm[d] = proj[m * HDIM + d];
    float kmaxh = g_kmax[h];
    const float ratio = rsqrtf((float)NBF);
    float ctx[HDIM];
    float kc = 0.f;
#pragma unroll
    for (int d = 0; d < HDIM; d++) ctx[d] = 0.f;

    for (int tile = blockIdx.x; tile < NTILES; tile += gridDim.x) {
        int row0 = tile * 32;
        __syncthreads();
        for (int i = t; i < 32 * 256; i += 352) {
            int r = i >> 8, d = i & 255;
            s[d][r] = (row0 + r < NN) ? g_C1[(size_t)(row0 + r) * 512 + 128 + d] : 0.f;
        }
        __syncthreads();
        int rmax = min(32, NN - row0);
        for (int r = 0; r < rmax; r++) {
            float dash = 0.f, diag = 0.f;
#pragma unroll
            for (int d = 0; d < HDIM; d++) {
                float kv = s[h * HDIM + d][r] * 0.5f;
                dash += kv * pm[d];
                diag += kv * kv;
            }
            float kpv = ratio * (fexp(dash - 0.5f * diag - kmaxh) + EPSV);
            kc += kpv;
#pragma unroll
            for (int d = 0; d < HDIM; d++) ctx[d] += kpv * s[128 + h * HDIM + d][r];
        }
    }
    atomicAdd(&g_kcum[h * NBF + m], kc);
#pragma unroll
    for (int d = 0; d < HDIM; d++) atomicAdd(&g_ctx[(h * HDIM + d) * NBF + m], ctx[d]);
}

// ---------------- attention output + h = elu(concat(gnn1, trans)) as hi/lo bf16 ----
__global__ __launch_bounds__(256) void attn_kernel(const float* __restrict__ proj) {
    __shared__ float qs[128][33];
    __shared__ float proj_s[NBF * HDIM];
    __shared__ float kcum_s[NHEADS * NBF];
    __shared__ float ctx_s[NHEADS * HDIM * NBF];
    int t = threadIdx.x;
    int row0 = blockIdx.x * 32;
    for (int i = t; i < NBF * HDIM; i += 256) proj_s[i] = proj[i];
    for (int i = t; i < NHEADS * NBF; i += 256) kcum_s[i] = g_kcum[i];
    for (int i = t; i < NHEADS * HDIM * NBF; i += 256) ctx_s[i] = g_ctx[i];
    for (int i = t; i < 32 * 128; i += 256) {
        int r = i >> 7, d = i & 127;
        qs[d][r] = (row0 + r < NN) ? g_C1[(size_t)(row0 + r) * 512 + d] : 0.f;
    }
    for (int i = t; i < 32 * 64; i += 256) {
        int r = i >> 6, dp = (i & 63) * 2;
        if (row0 + r < NN) {
            float2 v = *(const float2*)&g_C1[(size_t)(row0 + r) * 512 + 384 + dp];
            v.x = v.x > 0.f ? v.x : expm1f(v.x);
            v.y = v.y > 0.f ? v.y : expm1f(v.y);
            __nv_bfloat16 hx = __float2bfloat16(v.x), hy = __float2bfloat16(v.y);
            size_t idx = (size_t)(row0 + r) * 256 + dp;
            *(__nv_bfloat162*)&g_h_hi[idx] = __nv_bfloat162(hx, hy);
            *(__nv_bfloat162*)&g_h_lo[idx] =
                __nv_bfloat162(__float2bfloat16(v.x - __bfloat162float(hx)),
                               __float2bfloat16(v.y - __bfloat162float(hy)));
        }
    }
    __syncthreads();
    int h = t >> 5, r = t & 31;
    if (row0 + r >= NN) return;
    float q[HDIM];
    float diag = 0.f;
#pragma unroll
    for (int d = 0; d < HDIM; d++) {
        q[d] = qs[h * HDIM + d][r] * 0.5f;
        diag += q[d] * q[d];
    }
    diag *= 0.5f;
    float dash[NBF];
    float qmax = -3e38f;
#pragma unroll
    for (int m = 0; m < NBF; m++) {
        float s = 0.f;
#pragma unroll
        for (int d = 0; d < HDIM; d++) s += q[d] * proj_s[m * HDIM + d];
        dash[m] = s;
        qmax = fmaxf(qmax, s);
    }
    float den = 0.f;
    float outv[HDIM];
#pragma unroll
    for (int d = 0; d < HDIM; d++) outv[d] = 0.f;
    const float ratio = rsqrtf((float)NBF);
#pragma unroll
    for (int m = 0; m < NBF; m++) {
        float qp = ratio * (fexp(dash[m] - diag - qmax) + EPSV);
        den += qp * kcum_s[h * NBF + m];
#pragma unroll
        for (int d = 0; d < HDIM; d++) outv[d] += qp * ctx_s[(h * HDIM + d) * NBF + m];
    }
    float dinv = 1.f / den;
    size_t hbase = (size_t)(row0 + r) * 256 + HIDDIM + h * HDIM;
#pragma unroll
    for (int d = 0; d < HDIM; d += 2) {
        float x = outv[d] * dinv, y = outv[d + 1] * dinv;
        x = x > 0.f ? x : expm1f(x);
        y = y > 0.f ? y : expm1f(y);
        __nv_bfloat16 hx = __float2bfloat16(x), hy = __float2bfloat16(y);
        *(__nv_bfloat162*)&g_h_hi[hbase + d] = __nv_bfloat162(hx, hy);
        *(__nv_bfloat162*)&g_h_lo[hbase + d] =
            __nv_bfloat162(__float2bfloat16(x - __bfloat162float(hx)),
                           __float2bfloat16(y - __bfloat162float(hy)));
    }
}

// ---------------- APPNP graph prep ----------------
__global__ void deg_kernel(const int* __restrict__ col) {
    int e = blockIdx.x * blockDim.x + threadIdx.x;
    if (e < NEDGE) atomicAdd(&g_cnt[col[e]], 1);
}

__global__ __launch_bounds__(1024) void scan_kernel() {
    __shared__ int wsum[32];
    __shared__ int carry_s;
    int t = threadIdx.x;
    int lane = t & 31, wid = t >> 5;
    if (t == 0) carry_s = 0;
    __syncthreads();
    for (int base = 0; base < NN; base += 1024) {
        int i = base + t;
        int v = (i < NN) ? g_cnt[i] : 0;
        int x = v;
#pragma unroll
        for (int o = 1; o < 32; o <<= 1) {
            int y = __shfl_up_sync(0xffffffffu, x, o);
            if (lane >= o) x += y;
        }
        if (lane == 31) wsum[wid] = x;
        __syncthreads();
        if (wid == 0) {
            int s = wsum[lane];
#pragma unroll
            for (int o = 1; o < 32; o <<= 1) {
                int y = __shfl_up_sync(0xffffffffu, s, o);
                if (lane >= o) s += y;
            }
            wsum[lane] = s;
        }
        __syncthreads();
        int incl = x + (wid > 0 ? wsum[wid - 1] : 0);
        int carry = carry_s;
        if (i < NN) {
            int off = carry + incl - v;
            g_off[i] = off;
            g_cursor[i] = off;
            g_dis[i] = rsqrtf((float)(v + 1));
        }
        __syncthreads();
        if (t == 1023) carry_s = carry + incl;
        __syncthreads();
    }
    if (t == 0) g_off[NN] = carry_s;
}

__global__ void fill_kernel(const int* __restrict__ row, const int* __restrict__ col) {
    int e = blockIdx.x * blockDim.x + threadIdx.x;
    if (e >= NEDGE) return;
    int r = row[e], cl = col[e];
    int pos = atomicAdd(&g_cursor[cl], 1);
    g_csr[pos] = make_int2(r, __float_as_int(g_dis[r] * g_dis[cl]));
}

// ---------------- APPNP hop: warp per node, fp16 gathers, fp32 accumulate ----------
template <bool LAST>
__global__ __launch_bounds__(256) void hop_kernel(int stage, float* __restrict__ out,
                                                  int out_size) {
    int node = blockIdx.x * 8 + (threadIdx.x >> 5);
    if (node >= NN) return;
    int lane = threadIdx.x & 31;
    const __half* src = (stage == 0) ? g_x0h : ((stage & 1) ? g_ha : g_hb);
    __half* dst = (stage & 1) ? g_hb : g_ha;
    int s = g_off[node], e = g_off[node + 1];
    float di = g_dis[node];
    float2 x0v = *(const float2*)&g_x0[(size_t)node * 64 + lane * 2];
    float2 sv = __half22float2(*(const __half2*)&src[(size_t)node * 64 + lane * 2]);
    float ax = di * di * sv.x, ay = di * di * sv.y;
    int j = s;
    for (; j + 8 <= e; j += 8) {
#pragma unroll
        for (int u = 0; u < 8; u++) {
            int2 ce = g_csr[j + u];
            float wt = __int_as_float(ce.y);
            float2 v = __half22float2(*(const __half2*)&src[(size_t)ce.x * 64 + lane * 2]);
            ax += wt * v.x;
            ay += wt * v.y;
        }
    }
    for (; j < e; j++) {
        int2 ce = g_csr[j];
        float wt = __int_as_float(ce.y);
        float2 v = __half22float2(*(const __half2*)&src[(size_t)ce.x * 64 + lane * 2]);
        ax += wt * v.x;
        ay += wt * v.y;
    }
    float rx = (1.f - ALPHAV) * ax + ALPHAV * x0v.x;
    float ry = (1.f - ALPHAV) * ay + ALPHAV * x0v.y;
    if (!LAST) {
        *(__half2*)&dst[(size_t)node * 64 + lane * 2] = __floats2half2_rn(rx, ry);
    } else {
        float mx = fmaxf(rx, ry);
#pragma unroll
        for (int o = 16; o > 0; o >>= 1) mx = fmaxf(mx, __shfl_xor_sync(0xffffffffu, mx, o));
        float ss = __expf(rx - mx) + __expf(ry - mx);
#pragma unroll
        for (int o = 16; o > 0; o >>= 1) ss += __shfl_xor_sync(0xffffffffu, ss, o);
        float lse = mx + logf(ss);
        int i0 = node * 64 + lane * 2;
        if (i0 + 1 < out_size) *(float2*)&out[i0] = make_float2(rx - lse, ry - lse);
        int j0 = NN * 64 + i0;
        if (j0 + 1 < out_size) *(float2*)&out[j0] = make_float2(rx, ry);
    }
}

// ---------------- launch ----------------
extern "C" void kernel_launch(void* const* d_in, const int* in_sizes, int n_in,
                              void* d_out, int out_size) {
    if (n_in < 13) return;
    const float* data = (const float*)d_in[0];
    const int* ei = (const int*)d_in[1];
    const float* l1w = (const float*)d_in[2];
    const float* l1b = (const float*)d_in[3];
    const float* l2w = (const float*)d_in[4];
    const float* l2b = (const float*)d_in[5];
    const float* qw = (const float*)d_in[6];
    const float* qb = (const float*)d_in[7];
    const float* kw = (const float*)d_in[8];
    const float* kb = (const float*)d_in[9];
    const float* vw = (const float*)d_in[10];
    const float* vb = (const float*)d_in[11];
    const float* proj = (const float*)d_in[12];
    const int* row = ei;
    const int* col = ei + NEDGE;

    cudaFuncSetAttribute(hmma_gemm_kernel, cudaFuncAttributeMaxDynamicSharedMemorySize, HG_SMEM);
    cudaFuncSetAttribute(gemm2_kernel, cudaFuncAttributeMaxDynamicSharedMemorySize, G2_SMEM);

    pack_kernel<<<(512 * 256 + 512 + 64 * 256 + 255) / 256, 256>>>(qw, kw, vw, l1w, qb, kb, vb, l1b, l2w);
    conv_kernel<<<(NN * 256 / 4 + 255) / 256, 256>>>(data);
    init_kernel<<<(NN + 255) / 256, 256>>>();

    dim3 g1((NN + 127) / 128, 4);
    hmma_gemm_kernel<<<g1, 256, HG_SMEM>>>();

    kmax_kernel<<<NTILES, 256>>>(proj);
    kp_acc_kernel<<<KPB, 352>>>(proj);
    attn_kernel<<<NTILES, 256>>>(proj);

    gemm2_kernel<<<(NN + 127) / 128, 256, G2_SMEM>>>(l2b);

    deg_kernel<<<(NEDGE + 255) / 256, 256>>>(col);
    scan_kernel<<<1, 1024>>>();
    fill_kernel<<<(NEDGE + 255) / 256, 256>>>(row, col);

    for (int k = 0; k < 9; k++)
        hop_kernel<false><<<(NN + 7) / 8, 256>>>(k, nullptr, 0);
    hop_kernel<true><<<(NN + 7) / 8, 256>>>(9, (float*)d_out, out_size);
}